// round 1
// baseline (speedup 1.0000x reference)
#include <cuda_runtime.h>
#include <math.h>

#define Bdim 2
#define Tdim 2048
#define HID 2048
#define NH 32
#define NKV 8
#define HD 64
#define BT (Bdim * Tdim)   // 4096

// ---------------- scratch (device globals; no allocations allowed) ----------
__device__ float g_qt[(size_t)BT * NH * HD];    // [4096, 2048] pre-rope Q
__device__ float g_kt[(size_t)BT * NKV * HD];   // [4096, 512]
__device__ float g_vt[(size_t)BT * NKV * HD];   // [4096, 512]
__device__ float g_q [(size_t)Bdim * NH  * Tdim * HD];  // [B,NH,T,HD]
__device__ float g_k [(size_t)Bdim * NKV * Tdim * HD];  // [B,NKV,T,HD]
__device__ float g_v [(size_t)Bdim * NKV * Tdim * HD];  // [B,NKV,T,HD]
__device__ float g_attn[(size_t)BT * NH * HD];  // [4096, 2048] attn output

// ---------------- SGEMM: C[M,N] = A[M,K] * B[N,K]^T ------------------------
// 128x128 tile, BK=8, 256 threads, 8x8 micro-tile per thread.
__global__ __launch_bounds__(256) void sgemm_nt(const float* __restrict__ A,
                                                const float* __restrict__ Bm,
                                                float* __restrict__ C,
                                                int M, int N, int K) {
    __shared__ float As[8][132];
    __shared__ float Bs[8][132];
    const int tid = threadIdx.x;
    const int bm = blockIdx.y * 128;
    const int bn = blockIdx.x * 128;
    const int tx = tid & 15;
    const int ty = tid >> 4;
    const int lrow = tid >> 1;          // 0..127
    const int lcol = (tid & 1) * 4;     // 0 or 4

    const float* Aptr = A + (size_t)(bm + lrow) * K + lcol;
    const float* Bptr = Bm + (size_t)(bn + lrow) * K + lcol;

    float acc[8][8];
#pragma unroll
    for (int i = 0; i < 8; i++)
#pragma unroll
        for (int j = 0; j < 8; j++) acc[i][j] = 0.f;

    for (int k0 = 0; k0 < K; k0 += 8) {
        float4 av = *(const float4*)(Aptr + k0);
        float4 bv = *(const float4*)(Bptr + k0);
        As[lcol + 0][lrow] = av.x; As[lcol + 1][lrow] = av.y;
        As[lcol + 2][lrow] = av.z; As[lcol + 3][lrow] = av.w;
        Bs[lcol + 0][lrow] = bv.x; Bs[lcol + 1][lrow] = bv.y;
        Bs[lcol + 2][lrow] = bv.z; Bs[lcol + 3][lrow] = bv.w;
        __syncthreads();
#pragma unroll
        for (int kk = 0; kk < 8; kk++) {
            float a[8], b[8];
#pragma unroll
            for (int i = 0; i < 8; i++) a[i] = As[kk][ty * 8 + i];
#pragma unroll
            for (int j = 0; j < 8; j++) b[j] = Bs[kk][tx * 8 + j];
#pragma unroll
            for (int i = 0; i < 8; i++)
#pragma unroll
                for (int j = 0; j < 8; j++)
                    acc[i][j] = fmaf(a[i], b[j], acc[i][j]);
        }
        __syncthreads();
    }

#pragma unroll
    for (int i = 0; i < 8; i++) {
        float* cp = C + (size_t)(bm + ty * 8 + i) * N + bn + tx * 8;
        *(float4*)cp       = make_float4(acc[i][0], acc[i][1], acc[i][2], acc[i][3]);
        *(float4*)(cp + 4) = make_float4(acc[i][4], acc[i][5], acc[i][6], acc[i][7]);
    }
}

// ---------------- RoPE + head transpose ------------------------------------
// qt [BT, NH*HD] -> g_q [B,NH,T,HD] (roped)
// kt [BT, NKV*HD] -> g_k (roped); vt -> g_v (copy/transpose)
__global__ __launch_bounds__(256) void rope_reorder(const float* __restrict__ cosp,
                                                    const float* __restrict__ sinp) {
    const int token = blockIdx.x;
    const int b = token / Tdim;
    const int t = token % Tdim;
    __shared__ float cs[HD], sn[HD];
    if (threadIdx.x < HD) {
        cs[threadIdx.x] = cosp[(size_t)token * HD + threadIdx.x];
        sn[threadIdx.x] = sinp[(size_t)token * HD + threadIdx.x];
    }
    __syncthreads();

    // Q: NH heads, 32 pairs each
    for (int p = threadIdx.x; p < NH * 32; p += 256) {
        const int hh = p >> 5;
        const int d  = p & 31;
        const size_t src = (size_t)token * (NH * HD) + hh * HD + d;
        float x1 = g_qt[src];
        float x2 = g_qt[src + 32];
        float c = cs[d], s = sn[d];   // cos[d] == cos[d+32], sin likewise
        const size_t base = ((size_t)(b * NH + hh) * Tdim + t) * HD;
        g_q[base + d]      = x1 * c - x2 * s;
        g_q[base + d + 32] = x2 * c + x1 * s;
    }
    // K
    for (int p = threadIdx.x; p < NKV * 32; p += 256) {
        const int hh = p >> 5;
        const int d  = p & 31;
        const size_t src = (size_t)token * (NKV * HD) + hh * HD + d;
        float x1 = g_kt[src];
        float x2 = g_kt[src + 32];
        float c = cs[d], s = sn[d];
        const size_t base = ((size_t)(b * NKV + hh) * Tdim + t) * HD;
        g_k[base + d]      = x1 * c - x2 * s;
        g_k[base + d + 32] = x2 * c + x1 * s;
    }
    // V: plain transpose
    for (int e = threadIdx.x; e < NKV * HD; e += 256) {
        const int hh = e >> 6;
        const int d  = e & 63;
        g_v[((size_t)(b * NKV + hh) * Tdim + t) * HD + d] =
            g_vt[(size_t)token * (NKV * HD) + e];
    }
}

// ---------------- Flash attention (fp32, causal, GQA) ----------------------
// grid: (T/64, B*NH). block 256 (16x16 thread tile, 4x4 micro-tile).
// dyn smem: Qt[64][68] + Kt[64][68] + Ps[64][68] + Vs[64][64]
#define FA_SMEM_FLOATS (3 * 64 * 68 + 64 * 64)
__global__ __launch_bounds__(256) void flash_attn() {
    extern __shared__ float smem[];
    float* Qt = smem;                 // Qt[d*68 + r]  (scaled Q, transposed)
    float* Kt = smem + 64 * 68;      // Kt[d*68 + c]
    float* Ps = smem + 2 * 64 * 68;  // Ps[r*68 + c]
    float* Vs = smem + 3 * 64 * 68;  // Vs[c*64 + d]

    const int qtile = blockIdx.x;
    const int bh = blockIdx.y;        // b*NH + h
    const int b = bh / NH;
    const int h = bh % NH;
    const int kvh = h / (NH / NKV);
    const int tid = threadIdx.x;
    const int tx = tid & 15;
    const int ty = tid >> 4;

    const float* qptr = g_q + ((size_t)bh * Tdim + qtile * 64) * HD;
    const float* kptr = g_k + ((size_t)(b * NKV + kvh) * Tdim) * HD;
    const float* vptr = g_v + ((size_t)(b * NKV + kvh) * Tdim) * HD;

    // Load Q tile, transposed + pre-scaled by HD^-0.5
#pragma unroll
    for (int j = 0; j < 4; j++) {
        const int lin = tid + j * 256;
        const int r = lin >> 4;
        const int d4 = (lin & 15) * 4;
        float4 v = *(const float4*)(qptr + r * HD + d4);
        Qt[(d4 + 0) * 68 + r] = v.x * 0.125f;
        Qt[(d4 + 1) * 68 + r] = v.y * 0.125f;
        Qt[(d4 + 2) * 68 + r] = v.z * 0.125f;
        Qt[(d4 + 3) * 68 + r] = v.w * 0.125f;
    }

    float m[4], l[4], o[4][4];
#pragma unroll
    for (int i = 0; i < 4; i++) {
        m[i] = -1e30f; l[i] = 0.f;
#pragma unroll
        for (int j = 0; j < 4; j++) o[i][j] = 0.f;
    }
    __syncthreads();

    for (int kt = 0; kt <= qtile; kt++) {
        // Load K (transposed) and V (natural) tiles
#pragma unroll
        for (int j = 0; j < 4; j++) {
            const int lin = tid + j * 256;
            const int r = lin >> 4;
            const int d4 = (lin & 15) * 4;
            float4 kv = *(const float4*)(kptr + (size_t)(kt * 64 + r) * HD + d4);
            Kt[(d4 + 0) * 68 + r] = kv.x;
            Kt[(d4 + 1) * 68 + r] = kv.y;
            Kt[(d4 + 2) * 68 + r] = kv.z;
            Kt[(d4 + 3) * 68 + r] = kv.w;
            float4 vv = *(const float4*)(vptr + (size_t)(kt * 64 + r) * HD + d4);
            *(float4*)(Vs + r * 64 + d4) = vv;
        }
        __syncthreads();

        // S = Q K^T (scaled already)
        float s[4][4];
#pragma unroll
        for (int i = 0; i < 4; i++)
#pragma unroll
            for (int j = 0; j < 4; j++) s[i][j] = 0.f;
#pragma unroll 8
        for (int d = 0; d < 64; d++) {
            float a0 = Qt[d * 68 + ty * 4 + 0];
            float a1 = Qt[d * 68 + ty * 4 + 1];
            float a2 = Qt[d * 68 + ty * 4 + 2];
            float a3 = Qt[d * 68 + ty * 4 + 3];
            float b0 = Kt[d * 68 + tx * 4 + 0];
            float b1 = Kt[d * 68 + tx * 4 + 1];
            float b2 = Kt[d * 68 + tx * 4 + 2];
            float b3 = Kt[d * 68 + tx * 4 + 3];
            s[0][0] = fmaf(a0, b0, s[0][0]); s[0][1] = fmaf(a0, b1, s[0][1]);
            s[0][2] = fmaf(a0, b2, s[0][2]); s[0][3] = fmaf(a0, b3, s[0][3]);
            s[1][0] = fmaf(a1, b0, s[1][0]); s[1][1] = fmaf(a1, b1, s[1][1]);
            s[1][2] = fmaf(a1, b2, s[1][2]); s[1][3] = fmaf(a1, b3, s[1][3]);
            s[2][0] = fmaf(a2, b0, s[2][0]); s[2][1] = fmaf(a2, b1, s[2][1]);
            s[2][2] = fmaf(a2, b2, s[2][2]); s[2][3] = fmaf(a2, b3, s[2][3]);
            s[3][0] = fmaf(a3, b0, s[3][0]); s[3][1] = fmaf(a3, b1, s[3][1]);
            s[3][2] = fmaf(a3, b2, s[3][2]); s[3][3] = fmaf(a3, b3, s[3][3]);
        }

        // Causal mask (only the diagonal tile needs it)
        if (kt == qtile) {
#pragma unroll
            for (int i = 0; i < 4; i++) {
                const int qg = ty * 4 + i;
#pragma unroll
                for (int j = 0; j < 4; j++) {
                    if (tx * 4 + j > qg) s[i][j] = -1e30f;
                }
            }
        }

        // Online softmax (row reductions via shfl over the 16 tx lanes)
#pragma unroll
        for (int i = 0; i < 4; i++) {
            float rm = fmaxf(fmaxf(s[i][0], s[i][1]), fmaxf(s[i][2], s[i][3]));
            rm = fmaxf(rm, __shfl_xor_sync(0xffffffffu, rm, 1));
            rm = fmaxf(rm, __shfl_xor_sync(0xffffffffu, rm, 2));
            rm = fmaxf(rm, __shfl_xor_sync(0xffffffffu, rm, 4));
            rm = fmaxf(rm, __shfl_xor_sync(0xffffffffu, rm, 8));
            float mn = fmaxf(m[i], rm);
            float alpha = __expf(m[i] - mn);
            m[i] = mn;
            float rs = 0.f;
#pragma unroll
            for (int j = 0; j < 4; j++) {
                s[i][j] = __expf(s[i][j] - mn);
                rs += s[i][j];
            }
            rs += __shfl_xor_sync(0xffffffffu, rs, 1);
            rs += __shfl_xor_sync(0xffffffffu, rs, 2);
            rs += __shfl_xor_sync(0xffffffffu, rs, 4);
            rs += __shfl_xor_sync(0xffffffffu, rs, 8);
            l[i] = l[i] * alpha + rs;
#pragma unroll
            for (int j = 0; j < 4; j++) o[i][j] *= alpha;
        }

        // Stage P
#pragma unroll
        for (int i = 0; i < 4; i++)
            *(float4*)(Ps + (ty * 4 + i) * 68 + tx * 4) =
                make_float4(s[i][0], s[i][1], s[i][2], s[i][3]);
        __syncthreads();

        // O += P V
#pragma unroll 8
        for (int c = 0; c < 64; c++) {
            float a0 = Ps[(ty * 4 + 0) * 68 + c];
            float a1 = Ps[(ty * 4 + 1) * 68 + c];
            float a2 = Ps[(ty * 4 + 2) * 68 + c];
            float a3 = Ps[(ty * 4 + 3) * 68 + c];
            float b0 = Vs[c * 64 + tx * 4 + 0];
            float b1 = Vs[c * 64 + tx * 4 + 1];
            float b2 = Vs[c * 64 + tx * 4 + 2];
            float b3 = Vs[c * 64 + tx * 4 + 3];
            o[0][0] = fmaf(a0, b0, o[0][0]); o[0][1] = fmaf(a0, b1, o[0][1]);
            o[0][2] = fmaf(a0, b2, o[0][2]); o[0][3] = fmaf(a0, b3, o[0][3]);
            o[1][0] = fmaf(a1, b0, o[1][0]); o[1][1] = fmaf(a1, b1, o[1][1]);
            o[1][2] = fmaf(a1, b2, o[1][2]); o[1][3] = fmaf(a1, b3, o[1][3]);
            o[2][0] = fmaf(a2, b0, o[2][0]); o[2][1] = fmaf(a2, b1, o[2][1]);
            o[2][2] = fmaf(a2, b2, o[2][2]); o[2][3] = fmaf(a2, b3, o[2][3]);
            o[3][0] = fmaf(a3, b0, o[3][0]); o[3][1] = fmaf(a3, b1, o[3][1]);
            o[3][2] = fmaf(a3, b2, o[3][2]); o[3][3] = fmaf(a3, b3, o[3][3]);
        }
        __syncthreads();
    }

    // Epilogue: normalize + write to g_attn [b, t, h*HD + d]
    const size_t outbase = ((size_t)b * Tdim + qtile * 64) * (NH * HD) + h * HD;
#pragma unroll
    for (int i = 0; i < 4; i++) {
        const float inv = 1.0f / l[i];
        float4 r = make_float4(o[i][0] * inv, o[i][1] * inv,
                               o[i][2] * inv, o[i][3] * inv);
        *(float4*)(g_attn + outbase + (size_t)(ty * 4 + i) * (NH * HD) + tx * 4) = r;
    }
}

// ---------------- launch ----------------------------------------------------
extern "C" void kernel_launch(void* const* d_in, const int* in_sizes, int n_in,
                              void* d_out, int out_size) {
    const float* hidden = (const float*)d_in[0];
    const float* cosp   = (const float*)d_in[1];
    const float* sinp   = (const float*)d_in[2];
    const float* wq     = (const float*)d_in[3];
    const float* wk     = (const float*)d_in[4];
    const float* wv     = (const float*)d_in[5];
    const float* wo     = (const float*)d_in[6];
    float* out = (float*)d_out;

    float *qt, *kt, *vt, *attn;
    cudaGetSymbolAddress((void**)&qt,   g_qt);
    cudaGetSymbolAddress((void**)&kt,   g_kt);
    cudaGetSymbolAddress((void**)&vt,   g_vt);
    cudaGetSymbolAddress((void**)&attn, g_attn);

    // QKV projections
    dim3 gq(HID / 128, BT / 128);          // (16, 32)
    dim3 gkv((NKV * HD) / 128, BT / 128);  // (4, 32)
    sgemm_nt<<<gq, 256>>>(hidden, wq, qt, BT, NH * HD, HID);
    sgemm_nt<<<gkv, 256>>>(hidden, wk, kt, BT, NKV * HD, HID);
    sgemm_nt<<<gkv, 256>>>(hidden, wv, vt, BT, NKV * HD, HID);

    // RoPE + transpose
    rope_reorder<<<BT, 256>>>(cosp, sinp);

    // Flash attention
    const int fa_smem = FA_SMEM_FLOATS * sizeof(float);  // 68608 B
    cudaFuncSetAttribute(flash_attn, cudaFuncAttributeMaxDynamicSharedMemorySize,
                         fa_smem);
    flash_attn<<<dim3(Tdim / 64, Bdim * NH), 256, fa_smem>>>();

    // Output projection
    sgemm_nt<<<gq, 256>>>(attn, wo, out, BT, HID, HID);
}

// round 2
// speedup vs baseline: 1.0029x; 1.0029x over previous
#include <cuda_runtime.h>
#include <math.h>

#define Bdim 2
#define Tdim 2048
#define HID 2048
#define NH 32
#define NKV 8
#define HD 64
#define BT (Bdim * Tdim)   // 4096

// ---------------- scratch (device globals; no allocations allowed) ----------
__device__ float g_qt[(size_t)BT * NH * HD];    // [4096, 2048] pre-rope Q
__device__ float g_kt[(size_t)BT * NKV * HD];   // [4096, 512]
__device__ float g_vt[(size_t)BT * NKV * HD];   // [4096, 512]
__device__ float g_q [(size_t)Bdim * NH  * Tdim * HD];  // [B,NH,T,HD]
__device__ float g_k [(size_t)Bdim * NKV * Tdim * HD];  // [B,NKV,T,HD]
__device__ float g_v [(size_t)Bdim * NKV * Tdim * HD];  // [B,NKV,T,HD]
__device__ float g_attn[(size_t)BT * NH * HD];  // [4096, 2048] attn output

// ---------------- SGEMM: C[M,N] = A[M,K] * B[N,K]^T ------------------------
// 128x128 tile, BK=8, 256 threads, 8x8 micro-tile per thread.
__global__ __launch_bounds__(256) void sgemm_nt(const float* __restrict__ A,
                                                const float* __restrict__ Bm,
                                                float* __restrict__ C,
                                                int M, int N, int K) {
    __shared__ float As[8][132];
    __shared__ float Bs[8][132];
    const int tid = threadIdx.x;
    const int bm = blockIdx.y * 128;
    const int bn = blockIdx.x * 128;
    const int tx = tid & 15;
    const int ty = tid >> 4;
    const int lrow = tid >> 1;          // 0..127
    const int lcol = (tid & 1) * 4;     // 0 or 4

    const float* Aptr = A + (size_t)(bm + lrow) * K + lcol;
    const float* Bptr = Bm + (size_t)(bn + lrow) * K + lcol;

    float acc[8][8];
#pragma unroll
    for (int i = 0; i < 8; i++)
#pragma unroll
        for (int j = 0; j < 8; j++) acc[i][j] = 0.f;

    for (int k0 = 0; k0 < K; k0 += 8) {
        float4 av = *(const float4*)(Aptr + k0);
        float4 bv = *(const float4*)(Bptr + k0);
        As[lcol + 0][lrow] = av.x; As[lcol + 1][lrow] = av.y;
        As[lcol + 2][lrow] = av.z; As[lcol + 3][lrow] = av.w;
        Bs[lcol + 0][lrow] = bv.x; Bs[lcol + 1][lrow] = bv.y;
        Bs[lcol + 2][lrow] = bv.z; Bs[lcol + 3][lrow] = bv.w;
        __syncthreads();
#pragma unroll
        for (int kk = 0; kk < 8; kk++) {
            float a[8], b[8];
#pragma unroll
            for (int i = 0; i < 8; i++) a[i] = As[kk][ty * 8 + i];
#pragma unroll
            for (int j = 0; j < 8; j++) b[j] = Bs[kk][tx * 8 + j];
#pragma unroll
            for (int i = 0; i < 8; i++)
#pragma unroll
                for (int j = 0; j < 8; j++)
                    acc[i][j] = fmaf(a[i], b[j], acc[i][j]);
        }
        __syncthreads();
    }

#pragma unroll
    for (int i = 0; i < 8; i++) {
        float* cp = C + (size_t)(bm + ty * 8 + i) * N + bn + tx * 8;
        *(float4*)cp       = make_float4(acc[i][0], acc[i][1], acc[i][2], acc[i][3]);
        *(float4*)(cp + 4) = make_float4(acc[i][4], acc[i][5], acc[i][6], acc[i][7]);
    }
}

// ---------------- RoPE + head transpose ------------------------------------
// qt [BT, NH*HD] -> g_q [B,NH,T,HD] (roped)
// kt [BT, NKV*HD] -> g_k (roped); vt -> g_v (copy/transpose)
__global__ __launch_bounds__(256) void rope_reorder(const float* __restrict__ cosp,
                                                    const float* __restrict__ sinp) {
    const int token = blockIdx.x;
    const int b = token / Tdim;
    const int t = token % Tdim;
    __shared__ float cs[HD], sn[HD];
    if (threadIdx.x < HD) {
        cs[threadIdx.x] = cosp[(size_t)token * HD + threadIdx.x];
        sn[threadIdx.x] = sinp[(size_t)token * HD + threadIdx.x];
    }
    __syncthreads();

    // Q: NH heads, 32 pairs each
    for (int p = threadIdx.x; p < NH * 32; p += 256) {
        const int hh = p >> 5;
        const int d  = p & 31;
        const size_t src = (size_t)token * (NH * HD) + hh * HD + d;
        float x1 = g_qt[src];
        float x2 = g_qt[src + 32];
        float c = cs[d], s = sn[d];   // cos[d] == cos[d+32], sin likewise
        const size_t base = ((size_t)(b * NH + hh) * Tdim + t) * HD;
        g_q[base + d]      = x1 * c - x2 * s;
        g_q[base + d + 32] = x2 * c + x1 * s;
    }
    // K
    for (int p = threadIdx.x; p < NKV * 32; p += 256) {
        const int hh = p >> 5;
        const int d  = p & 31;
        const size_t src = (size_t)token * (NKV * HD) + hh * HD + d;
        float x1 = g_kt[src];
        float x2 = g_kt[src + 32];
        float c = cs[d], s = sn[d];
        const size_t base = ((size_t)(b * NKV + hh) * Tdim + t) * HD;
        g_k[base + d]      = x1 * c - x2 * s;
        g_k[base + d + 32] = x2 * c + x1 * s;
    }
    // V: plain transpose
    for (int e = threadIdx.x; e < NKV * HD; e += 256) {
        const int hh = e >> 6;
        const int d  = e & 63;
        g_v[((size_t)(b * NKV + hh) * Tdim + t) * HD + d] =
            g_vt[(size_t)token * (NKV * HD) + e];
    }
}

// ---------------- Flash attention (fp32, causal, GQA) ----------------------
// grid: (T/64, B*NH). block 256 (16x16 thread tile, 4x4 micro-tile).
// dyn smem: Qt[64][68] + Kt[64][68] + Ps[64][68] + Vs[64][64]
#define FA_SMEM_FLOATS (3 * 64 * 68 + 64 * 64)
__global__ __launch_bounds__(256) void flash_attn() {
    extern __shared__ float smem[];
    float* Qt = smem;                 // Qt[d*68 + r]  (scaled Q, transposed)
    float* Kt = smem + 64 * 68;      // Kt[d*68 + c]
    float* Ps = smem + 2 * 64 * 68;  // Ps[r*68 + c]
    float* Vs = smem + 3 * 64 * 68;  // Vs[c*64 + d]

    const int qtile = blockIdx.x;
    const int bh = blockIdx.y;        // b*NH + h
    const int b = bh / NH;
    const int h = bh % NH;
    const int kvh = h / (NH / NKV);
    const int tid = threadIdx.x;
    const int tx = tid & 15;
    const int ty = tid >> 4;

    const float* qptr = g_q + ((size_t)bh * Tdim + qtile * 64) * HD;
    const float* kptr = g_k + ((size_t)(b * NKV + kvh) * Tdim) * HD;
    const float* vptr = g_v + ((size_t)(b * NKV + kvh) * Tdim) * HD;

    // Load Q tile, transposed + pre-scaled by HD^-0.5
#pragma unroll
    for (int j = 0; j < 4; j++) {
        const int lin = tid + j * 256;
        const int r = lin >> 4;
        const int d4 = (lin & 15) * 4;
        float4 v = *(const float4*)(qptr + r * HD + d4);
        Qt[(d4 + 0) * 68 + r] = v.x * 0.125f;
        Qt[(d4 + 1) * 68 + r] = v.y * 0.125f;
        Qt[(d4 + 2) * 68 + r] = v.z * 0.125f;
        Qt[(d4 + 3) * 68 + r] = v.w * 0.125f;
    }

    float m[4], l[4], o[4][4];
#pragma unroll
    for (int i = 0; i < 4; i++) {
        m[i] = -1e30f; l[i] = 0.f;
#pragma unroll
        for (int j = 0; j < 4; j++) o[i][j] = 0.f;
    }
    __syncthreads();

    for (int kt = 0; kt <= qtile; kt++) {
        // Load K (transposed) and V (natural) tiles
#pragma unroll
        for (int j = 0; j < 4; j++) {
            const int lin = tid + j * 256;
            const int r = lin >> 4;
            const int d4 = (lin & 15) * 4;
            float4 kv = *(const float4*)(kptr + (size_t)(kt * 64 + r) * HD + d4);
            Kt[(d4 + 0) * 68 + r] = kv.x;
            Kt[(d4 + 1) * 68 + r] = kv.y;
            Kt[(d4 + 2) * 68 + r] = kv.z;
            Kt[(d4 + 3) * 68 + r] = kv.w;
            float4 vv = *(const float4*)(vptr + (size_t)(kt * 64 + r) * HD + d4);
            *(float4*)(Vs + r * 64 + d4) = vv;
        }
        __syncthreads();

        // S = Q K^T (scaled already)
        float s[4][4];
#pragma unroll
        for (int i = 0; i < 4; i++)
#pragma unroll
            for (int j = 0; j < 4; j++) s[i][j] = 0.f;
#pragma unroll 8
        for (int d = 0; d < 64; d++) {
            float a0 = Qt[d * 68 + ty * 4 + 0];
            float a1 = Qt[d * 68 + ty * 4 + 1];
            float a2 = Qt[d * 68 + ty * 4 + 2];
            float a3 = Qt[d * 68 + ty * 4 + 3];
            float b0 = Kt[d * 68 + tx * 4 + 0];
            float b1 = Kt[d * 68 + tx * 4 + 1];
            float b2 = Kt[d * 68 + tx * 4 + 2];
            float b3 = Kt[d * 68 + tx * 4 + 3];
            s[0][0] = fmaf(a0, b0, s[0][0]); s[0][1] = fmaf(a0, b1, s[0][1]);
            s[0][2] = fmaf(a0, b2, s[0][2]); s[0][3] = fmaf(a0, b3, s[0][3]);
            s[1][0] = fmaf(a1, b0, s[1][0]); s[1][1] = fmaf(a1, b1, s[1][1]);
            s[1][2] = fmaf(a1, b2, s[1][2]); s[1][3] = fmaf(a1, b3, s[1][3]);
            s[2][0] = fmaf(a2, b0, s[2][0]); s[2][1] = fmaf(a2, b1, s[2][1]);
            s[2][2] = fmaf(a2, b2, s[2][2]); s[2][3] = fmaf(a2, b3, s[2][3]);
            s[3][0] = fmaf(a3, b0, s[3][0]); s[3][1] = fmaf(a3, b1, s[3][1]);
            s[3][2] = fmaf(a3, b2, s[3][2]); s[3][3] = fmaf(a3, b3, s[3][3]);
        }

        // Causal mask (only the diagonal tile needs it)
        if (kt == qtile) {
#pragma unroll
            for (int i = 0; i < 4; i++) {
                const int qg = ty * 4 + i;
#pragma unroll
                for (int j = 0; j < 4; j++) {
                    if (tx * 4 + j > qg) s[i][j] = -1e30f;
                }
            }
        }

        // Online softmax (row reductions via shfl over the 16 tx lanes)
#pragma unroll
        for (int i = 0; i < 4; i++) {
            float rm = fmaxf(fmaxf(s[i][0], s[i][1]), fmaxf(s[i][2], s[i][3]));
            rm = fmaxf(rm, __shfl_xor_sync(0xffffffffu, rm, 1));
            rm = fmaxf(rm, __shfl_xor_sync(0xffffffffu, rm, 2));
            rm = fmaxf(rm, __shfl_xor_sync(0xffffffffu, rm, 4));
            rm = fmaxf(rm, __shfl_xor_sync(0xffffffffu, rm, 8));
            float mn = fmaxf(m[i], rm);
            float alpha = __expf(m[i] - mn);
            m[i] = mn;
            float rs = 0.f;
#pragma unroll
            for (int j = 0; j < 4; j++) {
                s[i][j] = __expf(s[i][j] - mn);
                rs += s[i][j];
            }
            rs += __shfl_xor_sync(0xffffffffu, rs, 1);
            rs += __shfl_xor_sync(0xffffffffu, rs, 2);
            rs += __shfl_xor_sync(0xffffffffu, rs, 4);
            rs += __shfl_xor_sync(0xffffffffu, rs, 8);
            l[i] = l[i] * alpha + rs;
#pragma unroll
            for (int j = 0; j < 4; j++) o[i][j] *= alpha;
        }

        // Stage P
#pragma unroll
        for (int i = 0; i < 4; i++)
            *(float4*)(Ps + (ty * 4 + i) * 68 + tx * 4) =
                make_float4(s[i][0], s[i][1], s[i][2], s[i][3]);
        __syncthreads();

        // O += P V
#pragma unroll 8
        for (int c = 0; c < 64; c++) {
            float a0 = Ps[(ty * 4 + 0) * 68 + c];
            float a1 = Ps[(ty * 4 + 1) * 68 + c];
            float a2 = Ps[(ty * 4 + 2) * 68 + c];
            float a3 = Ps[(ty * 4 + 3) * 68 + c];
            float b0 = Vs[c * 64 + tx * 4 + 0];
            float b1 = Vs[c * 64 + tx * 4 + 1];
            float b2 = Vs[c * 64 + tx * 4 + 2];
            float b3 = Vs[c * 64 + tx * 4 + 3];
            o[0][0] = fmaf(a0, b0, o[0][0]); o[0][1] = fmaf(a0, b1, o[0][1]);
            o[0][2] = fmaf(a0, b2, o[0][2]); o[0][3] = fmaf(a0, b3, o[0][3]);
            o[1][0] = fmaf(a1, b0, o[1][0]); o[1][1] = fmaf(a1, b1, o[1][1]);
            o[1][2] = fmaf(a1, b2, o[1][2]); o[1][3] = fmaf(a1, b3, o[1][3]);
            o[2][0] = fmaf(a2, b0, o[2][0]); o[2][1] = fmaf(a2, b1, o[2][1]);
            o[2][2] = fmaf(a2, b2, o[2][2]); o[2][3] = fmaf(a2, b3, o[2][3]);
            o[3][0] = fmaf(a3, b0, o[3][0]); o[3][1] = fmaf(a3, b1, o[3][1]);
            o[3][2] = fmaf(a3, b2, o[3][2]); o[3][3] = fmaf(a3, b3, o[3][3]);
        }
        __syncthreads();
    }

    // Epilogue: normalize + write to g_attn [b, t, h*HD + d]
    const size_t outbase = ((size_t)b * Tdim + qtile * 64) * (NH * HD) + h * HD;
#pragma unroll
    for (int i = 0; i < 4; i++) {
        const float inv = 1.0f / l[i];
        float4 r = make_float4(o[i][0] * inv, o[i][1] * inv,
                               o[i][2] * inv, o[i][3] * inv);
        *(float4*)(g_attn + outbase + (size_t)(ty * 4 + i) * (NH * HD) + tx * 4) = r;
    }
}

// ---------------- launch ----------------------------------------------------
extern "C" void kernel_launch(void* const* d_in, const int* in_sizes, int n_in,
                              void* d_out, int out_size) {
    const float* hidden = (const float*)d_in[0];
    const float* cosp   = (const float*)d_in[1];
    const float* sinp   = (const float*)d_in[2];
    const float* wq     = (const float*)d_in[3];
    const float* wk     = (const float*)d_in[4];
    const float* wv     = (const float*)d_in[5];
    const float* wo     = (const float*)d_in[6];
    float* out = (float*)d_out;

    float *qt, *kt, *vt, *attn;
    cudaGetSymbolAddress((void**)&qt,   g_qt);
    cudaGetSymbolAddress((void**)&kt,   g_kt);
    cudaGetSymbolAddress((void**)&vt,   g_vt);
    cudaGetSymbolAddress((void**)&attn, g_attn);

    // QKV projections
    dim3 gq(HID / 128, BT / 128);          // (16, 32)
    dim3 gkv((NKV * HD) / 128, BT / 128);  // (4, 32)
    sgemm_nt<<<gq, 256>>>(hidden, wq, qt, BT, NH * HD, HID);
    sgemm_nt<<<gkv, 256>>>(hidden, wk, kt, BT, NKV * HD, HID);
    sgemm_nt<<<gkv, 256>>>(hidden, wv, vt, BT, NKV * HD, HID);

    // RoPE + transpose
    rope_reorder<<<BT, 256>>>(cosp, sinp);

    // Flash attention
    const int fa_smem = FA_SMEM_FLOATS * sizeof(float);  // 68608 B
    cudaFuncSetAttribute(flash_attn, cudaFuncAttributeMaxDynamicSharedMemorySize,
                         fa_smem);
    flash_attn<<<dim3(Tdim / 64, Bdim * NH), 256, fa_smem>>>();

    // Output projection
    sgemm_nt<<<gq, 256>>>(attn, wo, out, BT, HID, HID);
}

// round 5
// speedup vs baseline: 1.7878x; 1.7827x over previous
#include <cuda_runtime.h>
#include <cstdint>
#include <math.h>

#define Bdim 2
#define Tdim 2048
#define HID 2048
#define NH 32
#define NKV 8
#define HD 64
#define BT (Bdim * Tdim)   // 4096

// ---------------- scratch (device globals; no allocations allowed) ----------
__device__ float g_qt[(size_t)BT * NH * HD];    // [4096, 2048] pre-rope Q
__device__ float g_kt[(size_t)BT * NKV * HD];   // [4096, 512]
__device__ float g_vt[(size_t)BT * NKV * HD];   // [4096, 512]
__device__ float g_q [(size_t)Bdim * NH  * Tdim * HD];  // [B,NH,T,HD]
__device__ float g_k [(size_t)Bdim * NKV * Tdim * HD];  // [B,NKV,T,HD]
__device__ float g_v [(size_t)Bdim * NKV * Tdim * HD];  // [B,NKV,T,HD]
__device__ float g_attn[(size_t)BT * NH * HD];  // [4096, 2048] attn output

// ======================= helpers ============================================
static __device__ __forceinline__ uint32_t smem_u32(const void* p) {
    uint32_t a;
    asm("{ .reg .u64 t; cvta.to.shared.u64 t, %1; cvt.u32.u64 %0, t; }"
        : "=r"(a) : "l"(p));
    return a;
}

static __device__ __forceinline__ void ldm4(uint32_t* r, uint32_t addr) {
    asm volatile("ldmatrix.sync.aligned.m8n8.x4.shared.b16 {%0,%1,%2,%3}, [%4];"
                 : "=r"(r[0]), "=r"(r[1]), "=r"(r[2]), "=r"(r[3]) : "r"(addr));
}

static __device__ __forceinline__ void mma16816(float* c, const uint32_t* a,
                                                uint32_t b0, uint32_t b1) {
    asm volatile("mma.sync.aligned.m16n8k16.row.col.f32.bf16.bf16.f32 "
                 "{%0,%1,%2,%3}, {%4,%5,%6,%7}, {%8,%9}, {%0,%1,%2,%3};"
                 : "+f"(c[0]), "+f"(c[1]), "+f"(c[2]), "+f"(c[3])
                 : "r"(a[0]), "r"(a[1]), "r"(a[2]), "r"(a[3]), "r"(b0), "r"(b1));
}

// float4 -> bf16 hi (truncate; exact) + bf16 lo (rounded residual); 8B stores.
static __device__ __forceinline__ void cvt_st(float4 f, uint32_t hi, uint32_t lo) {
    uint32_t xu = __float_as_uint(f.x), yu = __float_as_uint(f.y);
    uint32_t zu = __float_as_uint(f.z), wu = __float_as_uint(f.w);
    uint32_t h01 = __byte_perm(xu, yu, 0x7632);
    uint32_t h23 = __byte_perm(zu, wu, 0x7632);
    float lx = f.x - __uint_as_float(xu & 0xFFFF0000u);
    float ly = f.y - __uint_as_float(yu & 0xFFFF0000u);
    float lz = f.z - __uint_as_float(zu & 0xFFFF0000u);
    float lw = f.w - __uint_as_float(wu & 0xFFFF0000u);
    uint32_t l01, l23;
    asm("cvt.rn.satfinite.bf16x2.f32 %0, %1, %2;" : "=r"(l01) : "f"(ly), "f"(lx));
    asm("cvt.rn.satfinite.bf16x2.f32 %0, %1, %2;" : "=r"(l23) : "f"(lw), "f"(lz));
    asm volatile("st.shared.v2.b32 [%0], {%1, %2};" :: "r"(hi), "r"(h01), "r"(h23) : "memory");
    asm volatile("st.shared.v2.b32 [%0], {%1, %2};" :: "r"(lo), "r"(l01), "r"(l23) : "memory");
}

// =============== mma.sync GEMM: C[M,N] = A[M,K] * B[N,K]^T ==================
// 128x128 CTA tile, BK=32, 256 threads (8 warps = 4m x 2n, 32x64 warp tile).
// 3x bf16 split (AhBh + AhBl + AlBh), fp32 accum. Double-buffered smem.
// smem tile: bf16 [128 rows][32 cols], row stride 80 B (64 data + 16 pad).
#define G_ROWB 80
#define G_TILE 10240                  // 128 * 80 bytes
#define G_STAGE_B (4 * G_TILE)        // Ah, Al, Bh, Bl = 40960
#define G_SMEM (2 * G_STAGE_B + 128)  // 82048

__global__ __launch_bounds__(256, 2) void gemm_mma(const float* __restrict__ A,
                                                   const float* __restrict__ Bm,
                                                   float* __restrict__ C,
                                                   int M, int N, int K) {
    extern __shared__ char dsm[];
    const uint32_t tile = (smem_u32(dsm) + 127u) & ~127u;

    const int tid = threadIdx.x;
    const int wid = tid >> 5;
    const int lane = tid & 31;
    const int wm = wid & 3;           // 0..3 (m)
    const int wn = wid >> 2;          // 0..1 (n)
    const int bm = blockIdx.y * 128;
    const int bn = blockIdx.x * 128;

    // loader mapping: 2 threads per row, each 16 cols (4 float4)
    const int lrow = tid >> 1;
    const int lc16 = (tid & 1) * 16;
    const float* Abase = A + (size_t)(bm + lrow) * K + lc16;
    const float* Bbase = Bm + (size_t)(bn + lrow) * K + lc16;
    const uint32_t s_row = (uint32_t)(lrow * G_ROWB + lc16 * 2);

    // ldmatrix lane offsets (bytes)
    const int r8 = lane & 7, sub = lane >> 3;
    const uint32_t a_off = (uint32_t)((wm * 32 + r8 + (sub & 1) * 8) * G_ROWB +
                                      (sub >> 1) * 16);
    const uint32_t b_off = (uint32_t)((wn * 64 + r8 + (sub >> 1) * 8) * G_ROWB +
                                      (sub & 1) * 16);

    float acc[2][8][4];
#pragma unroll
    for (int i = 0; i < 2; i++)
#pragma unroll
        for (int j = 0; j < 8; j++)
#pragma unroll
            for (int q = 0; q < 4; q++) acc[i][j][q] = 0.f;

    const int nch = K >> 5;   // K / 32

    // prologue: chunk 0 -> buf 0
    {
        const uint32_t sb = tile;
#pragma unroll
        for (int j = 0; j < 4; j++) {
            float4 fa = *(const float4*)(Abase + j * 4);
            cvt_st(fa, sb + s_row + j * 8, sb + G_TILE + s_row + j * 8);
            float4 fb = *(const float4*)(Bbase + j * 4);
            cvt_st(fb, sb + 2 * G_TILE + s_row + j * 8,
                       sb + 3 * G_TILE + s_row + j * 8);
        }
    }
    __syncthreads();

    for (int i = 0; i < nch; i++) {
        const uint32_t cur = tile + (uint32_t)(i & 1) * G_STAGE_B;
        // load chunk i+1 into other buffer (overlaps with mma below)
        if (i + 1 < nch) {
            const uint32_t nb = tile + (uint32_t)((i + 1) & 1) * G_STAGE_B;
            const int k0 = (i + 1) << 5;
#pragma unroll
            for (int j = 0; j < 4; j++) {
                float4 fa = *(const float4*)(Abase + k0 + j * 4);
                cvt_st(fa, nb + s_row + j * 8, nb + G_TILE + s_row + j * 8);
                float4 fb = *(const float4*)(Bbase + k0 + j * 4);
                cvt_st(fb, nb + 2 * G_TILE + s_row + j * 8,
                           nb + 3 * G_TILE + s_row + j * 8);
            }
        }

        // compute chunk i: two k16 steps
#pragma unroll
        for (int ks = 0; ks < 2; ks++) {
            uint32_t ah[8], al[8];
            const uint32_t ka = cur + a_off + ks * 32;
            ldm4(ah,     ka);
            ldm4(ah + 4, ka + 16 * G_ROWB);
            ldm4(al,     ka + G_TILE);
            ldm4(al + 4, ka + G_TILE + 16 * G_ROWB);
#pragma unroll
            for (int g = 0; g < 4; g++) {
                uint32_t bh[4], bl[4];
                const uint32_t kb = cur + 2 * G_TILE + b_off + ks * 32 +
                                    g * (16 * G_ROWB);
                ldm4(bh, kb);
                ldm4(bl, kb + G_TILE);
#pragma unroll
                for (int ms = 0; ms < 2; ms++) {
                    mma16816(acc[ms][2 * g],     ah + 4 * ms, bh[0], bh[1]);
                    mma16816(acc[ms][2 * g + 1], ah + 4 * ms, bh[2], bh[3]);
                    mma16816(acc[ms][2 * g],     ah + 4 * ms, bl[0], bl[1]);
                    mma16816(acc[ms][2 * g + 1], ah + 4 * ms, bl[2], bl[3]);
                    mma16816(acc[ms][2 * g],     al + 4 * ms, bh[0], bh[1]);
                    mma16816(acc[ms][2 * g + 1], al + 4 * ms, bh[2], bh[3]);
                }
            }
        }
        __syncthreads();
    }

    // epilogue
    const int trow = lane >> 2;
    const int tcol = (lane & 3) * 2;
#pragma unroll
    for (int ms = 0; ms < 2; ms++) {
#pragma unroll
        for (int nf = 0; nf < 8; nf++) {
            const int r = bm + wm * 32 + ms * 16 + trow;
            const int c = bn + wn * 64 + nf * 8 + tcol;
            *(float2*)(C + (size_t)r * N + c) =
                make_float2(acc[ms][nf][0], acc[ms][nf][1]);
            *(float2*)(C + (size_t)(r + 8) * N + c) =
                make_float2(acc[ms][nf][2], acc[ms][nf][3]);
        }
    }
}

// ---------------- RoPE + head transpose ------------------------------------
__global__ __launch_bounds__(256) void rope_reorder(const float* __restrict__ cosp,
                                                    const float* __restrict__ sinp) {
    const int token = blockIdx.x;
    const int b = token / Tdim;
    const int t = token % Tdim;
    __shared__ float cs[HD], sn[HD];
    if (threadIdx.x < HD) {
        cs[threadIdx.x] = cosp[(size_t)token * HD + threadIdx.x];
        sn[threadIdx.x] = sinp[(size_t)token * HD + threadIdx.x];
    }
    __syncthreads();

    for (int p = threadIdx.x; p < NH * 32; p += 256) {
        const int hh = p >> 5;
        const int d  = p & 31;
        const size_t src = (size_t)token * (NH * HD) + hh * HD + d;
        float x1 = g_qt[src];
        float x2 = g_qt[src + 32];
        float c = cs[d], s = sn[d];
        const size_t base = ((size_t)(b * NH + hh) * Tdim + t) * HD;
        g_q[base + d]      = x1 * c - x2 * s;
        g_q[base + d + 32] = x2 * c + x1 * s;
    }
    for (int p = threadIdx.x; p < NKV * 32; p += 256) {
        const int hh = p >> 5;
        const int d  = p & 31;
        const size_t src = (size_t)token * (NKV * HD) + hh * HD + d;
        float x1 = g_kt[src];
        float x2 = g_kt[src + 32];
        float c = cs[d], s = sn[d];
        const size_t base = ((size_t)(b * NKV + hh) * Tdim + t) * HD;
        g_k[base + d]      = x1 * c - x2 * s;
        g_k[base + d + 32] = x2 * c + x1 * s;
    }
    for (int e = threadIdx.x; e < NKV * HD; e += 256) {
        const int hh = e >> 6;
        const int d  = e & 63;
        g_v[((size_t)(b * NKV + hh) * Tdim + t) * HD + d] =
            g_vt[(size_t)token * (NKV * HD) + e];
    }
}

// ---------------- Flash attention (fp32, causal, GQA) ----------------------
// Br=128, Bc=64. 256 threads: ty(0..15) x 8 rows, tx(0..15) x 4 cols.
// dyn smem floats: Qt[64][132] + Kt[64][68] + Ps[128][68] + Vs[64][64]
#define FA_SMEM_FLOATS (64 * 132 + 64 * 68 + 128 * 68 + 64 * 64)  // 25600
__global__ __launch_bounds__(256) void flash_attn2() {
    extern __shared__ float fsm[];
    float* Qt = fsm;                       // [d][r] stride 132
    float* Kt = fsm + 64 * 132;            // [d][c] stride 68
    float* Ps = Kt + 64 * 68;              // [r][c] stride 68
    float* Vs = Ps + 128 * 68;             // [c][d] stride 64

    const int qtile = (int)gridDim.x - 1 - (int)blockIdx.x;  // big tiles first
    const int bh = blockIdx.y;
    const int b = bh / NH;
    const int h = bh % NH;
    const int kvh = h / (NH / NKV);
    const int tid = threadIdx.x;
    const int tx = tid & 15;
    const int ty = tid >> 4;

    const float* qptr = g_q + ((size_t)bh * Tdim + qtile * 128) * HD;
    const float* kptr = g_k + ((size_t)(b * NKV + kvh) * Tdim) * HD;
    const float* vptr = g_v + ((size_t)(b * NKV + kvh) * Tdim) * HD;

#pragma unroll
    for (int j = 0; j < 8; j++) {
        const int lin = tid + j * 256;
        const int r = lin >> 4;
        const int d4 = (lin & 15) * 4;
        float4 v = *(const float4*)(qptr + (size_t)r * HD + d4);
        Qt[(d4 + 0) * 132 + r] = v.x * 0.125f;
        Qt[(d4 + 1) * 132 + r] = v.y * 0.125f;
        Qt[(d4 + 2) * 132 + r] = v.z * 0.125f;
        Qt[(d4 + 3) * 132 + r] = v.w * 0.125f;
    }

    float m[8], l[8], o[8][4];
#pragma unroll
    for (int i = 0; i < 8; i++) {
        m[i] = -1e30f; l[i] = 0.f;
#pragma unroll
        for (int j = 0; j < 4; j++) o[i][j] = 0.f;
    }
    __syncthreads();

    const int ktmax = 2 * qtile + 1;
    for (int kt = 0; kt <= ktmax; kt++) {
#pragma unroll
        for (int j = 0; j < 4; j++) {
            const int lin = tid + j * 256;
            const int r = lin >> 4;
            const int d4 = (lin & 15) * 4;
            float4 kv = *(const float4*)(kptr + (size_t)(kt * 64 + r) * HD + d4);
            Kt[(d4 + 0) * 68 + r] = kv.x;
            Kt[(d4 + 1) * 68 + r] = kv.y;
            Kt[(d4 + 2) * 68 + r] = kv.z;
            Kt[(d4 + 3) * 68 + r] = kv.w;
            float4 vv = *(const float4*)(vptr + (size_t)(kt * 64 + r) * HD + d4);
            *(float4*)(Vs + r * 64 + d4) = vv;
        }
        __syncthreads();

        float s[8][4];
#pragma unroll
        for (int i = 0; i < 8; i++)
#pragma unroll
            for (int j = 0; j < 4; j++) s[i][j] = 0.f;

#pragma unroll 8
        for (int d = 0; d < 64; d++) {
            float4 a0 = *(const float4*)(Qt + d * 132 + ty * 8);
            float4 a1 = *(const float4*)(Qt + d * 132 + ty * 8 + 4);
            float4 bv = *(const float4*)(Kt + d * 68 + tx * 4);
            float a[8] = {a0.x, a0.y, a0.z, a0.w, a1.x, a1.y, a1.z, a1.w};
#pragma unroll
            for (int i = 0; i < 8; i++) {
                s[i][0] = fmaf(a[i], bv.x, s[i][0]);
                s[i][1] = fmaf(a[i], bv.y, s[i][1]);
                s[i][2] = fmaf(a[i], bv.z, s[i][2]);
                s[i][3] = fmaf(a[i], bv.w, s[i][3]);
            }
        }

        if (kt >= 2 * qtile) {
#pragma unroll
            for (int i = 0; i < 8; i++) {
                const int qg = qtile * 128 + ty * 8 + i;
#pragma unroll
                for (int j = 0; j < 4; j++) {
                    if (kt * 64 + tx * 4 + j > qg) s[i][j] = -1e30f;
                }
            }
        }

#pragma unroll
        for (int i = 0; i < 8; i++) {
            float rm = fmaxf(fmaxf(s[i][0], s[i][1]), fmaxf(s[i][2], s[i][3]));
            rm = fmaxf(rm, __shfl_xor_sync(0xffffffffu, rm, 1));
            rm = fmaxf(rm, __shfl_xor_sync(0xffffffffu, rm, 2));
            rm = fmaxf(rm, __shfl_xor_sync(0xffffffffu, rm, 4));
            rm = fmaxf(rm, __shfl_xor_sync(0xffffffffu, rm, 8));
            float mn = fmaxf(m[i], rm);
            float alpha = __expf(m[i] - mn);
            m[i] = mn;
            float rs = 0.f;
#pragma unroll
            for (int j = 0; j < 4; j++) {
                s[i][j] = __expf(s[i][j] - mn);
                rs += s[i][j];
            }
            rs += __shfl_xor_sync(0xffffffffu, rs, 1);
            rs += __shfl_xor_sync(0xffffffffu, rs, 2);
            rs += __shfl_xor_sync(0xffffffffu, rs, 4);
            rs += __shfl_xor_sync(0xffffffffu, rs, 8);
            l[i] = l[i] * alpha + rs;
#pragma unroll
            for (int j = 0; j < 4; j++) o[i][j] *= alpha;
        }

#pragma unroll
        for (int i = 0; i < 8; i++)
            *(float4*)(Ps + (ty * 8 + i) * 68 + tx * 4) =
                make_float4(s[i][0], s[i][1], s[i][2], s[i][3]);
        __syncthreads();

#pragma unroll 8
        for (int c = 0; c < 64; c++) {
            float4 bv = *(const float4*)(Vs + c * 64 + tx * 4);
#pragma unroll
            for (int i = 0; i < 8; i++) {
                float a = Ps[(ty * 8 + i) * 68 + c];
                o[i][0] = fmaf(a, bv.x, o[i][0]);
                o[i][1] = fmaf(a, bv.y, o[i][1]);
                o[i][2] = fmaf(a, bv.z, o[i][2]);
                o[i][3] = fmaf(a, bv.w, o[i][3]);
            }
        }
        __syncthreads();
    }

#pragma unroll
    for (int i = 0; i < 8; i++) {
        const int row = qtile * 128 + ty * 8 + i;
        const float inv = 1.0f / l[i];
        *(float4*)(g_attn + ((size_t)b * Tdim + row) * (NH * HD) + h * HD + tx * 4) =
            make_float4(o[i][0] * inv, o[i][1] * inv, o[i][2] * inv, o[i][3] * inv);
    }
}

// ---------------- launch ----------------------------------------------------
extern "C" void kernel_launch(void* const* d_in, const int* in_sizes, int n_in,
                              void* d_out, int out_size) {
    const float* hidden = (const float*)d_in[0];
    const float* cosp   = (const float*)d_in[1];
    const float* sinp   = (const float*)d_in[2];
    const float* wq     = (const float*)d_in[3];
    const float* wk     = (const float*)d_in[4];
    const float* wv     = (const float*)d_in[5];
    const float* wo     = (const float*)d_in[6];
    float* out = (float*)d_out;

    float *qt, *kt, *vt, *attn;
    cudaGetSymbolAddress((void**)&qt,   g_qt);
    cudaGetSymbolAddress((void**)&kt,   g_kt);
    cudaGetSymbolAddress((void**)&vt,   g_vt);
    cudaGetSymbolAddress((void**)&attn, g_attn);

    cudaFuncSetAttribute(gemm_mma, cudaFuncAttributeMaxDynamicSharedMemorySize,
                         G_SMEM);
    const int fa_smem = FA_SMEM_FLOATS * sizeof(float);  // 102400 B
    cudaFuncSetAttribute(flash_attn2, cudaFuncAttributeMaxDynamicSharedMemorySize,
                         fa_smem);

    // QKV projections (mma.sync bf16, 3x split)
    gemm_mma<<<dim3(16, 32), 256, G_SMEM>>>(hidden, wq, qt, BT, NH * HD, HID);
    gemm_mma<<<dim3(4, 32),  256, G_SMEM>>>(hidden, wk, kt, BT, NKV * HD, HID);
    gemm_mma<<<dim3(4, 32),  256, G_SMEM>>>(hidden, wv, vt, BT, NKV * HD, HID);

    // RoPE + transpose
    rope_reorder<<<BT, 256>>>(cosp, sinp);

    // Flash attention (fp32)
    flash_attn2<<<dim3(Tdim / 128, Bdim * NH), 256, fa_smem>>>();

    // Output projection
    gemm_mma<<<dim3(16, 32), 256, G_SMEM>>>(attn, wo, out, BT, HID, HID);
}

// round 6
// speedup vs baseline: 1.7884x; 1.0003x over previous
#include <cuda_runtime.h>
#include <cstdint>
#include <math.h>

#define Bdim 2
#define Tdim 2048
#define HID 2048
#define NH 32
#define NKV 8
#define HD 64
#define BT (Bdim * Tdim)   // 4096

// ---------------- scratch (device globals; no allocations allowed) ----------
__device__ float g_qt[(size_t)BT * NH * HD];    // [4096, 2048] pre-rope Q
__device__ float g_kt[(size_t)BT * NKV * HD];   // [4096, 512]
__device__ float g_vt[(size_t)BT * NKV * HD];   // [4096, 512]
__device__ float g_q [(size_t)Bdim * NH  * Tdim * HD];  // [B,NH,T,HD]
__device__ float g_k [(size_t)Bdim * NKV * Tdim * HD];  // [B,NKV,T,HD]
__device__ float g_v [(size_t)Bdim * NKV * Tdim * HD];  // [B,NKV,T,HD]
__device__ float g_attn[(size_t)BT * NH * HD];  // [4096, 2048] attn output

// ======================= helpers ============================================
static __device__ __forceinline__ uint32_t smem_u32(const void* p) {
    uint32_t a;
    asm("{ .reg .u64 t; cvta.to.shared.u64 t, %1; cvt.u32.u64 %0, t; }"
        : "=r"(a) : "l"(p));
    return a;
}

static __device__ __forceinline__ void ldm4(uint32_t* r, uint32_t addr) {
    asm volatile("ldmatrix.sync.aligned.m8n8.x4.shared.b16 {%0,%1,%2,%3}, [%4];"
                 : "=r"(r[0]), "=r"(r[1]), "=r"(r[2]), "=r"(r[3]) : "r"(addr));
}

static __device__ __forceinline__ void mma16816(float* c, const uint32_t* a,
                                                uint32_t b0, uint32_t b1) {
    asm volatile("mma.sync.aligned.m16n8k16.row.col.f32.bf16.bf16.f32 "
                 "{%0,%1,%2,%3}, {%4,%5,%6,%7}, {%8,%9}, {%0,%1,%2,%3};"
                 : "+f"(c[0]), "+f"(c[1]), "+f"(c[2]), "+f"(c[3])
                 : "r"(a[0]), "r"(a[1]), "r"(a[2]), "r"(a[3]), "r"(b0), "r"(b1));
}

// float4 -> bf16 hi (truncate; exact) + bf16 lo (rounded residual); 8B stores.
static __device__ __forceinline__ void cvt_st(float4 f, uint32_t hi, uint32_t lo) {
    uint32_t xu = __float_as_uint(f.x), yu = __float_as_uint(f.y);
    uint32_t zu = __float_as_uint(f.z), wu = __float_as_uint(f.w);
    uint32_t h01 = __byte_perm(xu, yu, 0x7632);
    uint32_t h23 = __byte_perm(zu, wu, 0x7632);
    float lx = f.x - __uint_as_float(xu & 0xFFFF0000u);
    float ly = f.y - __uint_as_float(yu & 0xFFFF0000u);
    float lz = f.z - __uint_as_float(zu & 0xFFFF0000u);
    float lw = f.w - __uint_as_float(wu & 0xFFFF0000u);
    uint32_t l01, l23;
    asm("cvt.rn.satfinite.bf16x2.f32 %0, %1, %2;" : "=r"(l01) : "f"(ly), "f"(lx));
    asm("cvt.rn.satfinite.bf16x2.f32 %0, %1, %2;" : "=r"(l23) : "f"(lw), "f"(lz));
    asm volatile("st.shared.v2.b32 [%0], {%1, %2};" :: "r"(hi), "r"(h01), "r"(h23) : "memory");
    asm volatile("st.shared.v2.b32 [%0], {%1, %2};" :: "r"(lo), "r"(l01), "r"(l23) : "memory");
}

// =============== mma.sync GEMM: C[M,N] = A[M,K] * B[N,K]^T ==================
// 128x128 CTA tile, BK=32, 256 threads (8 warps = 4m x 2n, 32x64 warp tile).
// 3x bf16 split (AhBh + AhBl + AlBh), fp32 accum. Double-buffered smem.
// smem tile: bf16 [128 rows][32 cols], row stride 80 B (64 data + 16 pad).
#define G_ROWB 80
#define G_TILE 10240                  // 128 * 80 bytes
#define G_STAGE_B (4 * G_TILE)        // Ah, Al, Bh, Bl = 40960
#define G_SMEM (2 * G_STAGE_B + 128)  // 82048

__global__ __launch_bounds__(256, 2) void gemm_mma(const float* __restrict__ A,
                                                   const float* __restrict__ Bm,
                                                   float* __restrict__ C,
                                                   int M, int N, int K) {
    extern __shared__ char dsm[];
    const uint32_t tile = (smem_u32(dsm) + 127u) & ~127u;

    const int tid = threadIdx.x;
    const int wid = tid >> 5;
    const int lane = tid & 31;
    const int wm = wid & 3;           // 0..3 (m)
    const int wn = wid >> 2;          // 0..1 (n)
    const int bm = blockIdx.y * 128;
    const int bn = blockIdx.x * 128;

    // loader mapping: 2 threads per row, each 16 cols (4 float4)
    const int lrow = tid >> 1;
    const int lc16 = (tid & 1) * 16;
    const float* Abase = A + (size_t)(bm + lrow) * K + lc16;
    const float* Bbase = Bm + (size_t)(bn + lrow) * K + lc16;
    const uint32_t s_row = (uint32_t)(lrow * G_ROWB + lc16 * 2);

    // ldmatrix lane offsets (bytes)
    const int r8 = lane & 7, sub = lane >> 3;
    const uint32_t a_off = (uint32_t)((wm * 32 + r8 + (sub & 1) * 8) * G_ROWB +
                                      (sub >> 1) * 16);
    const uint32_t b_off = (uint32_t)((wn * 64 + r8 + (sub >> 1) * 8) * G_ROWB +
                                      (sub & 1) * 16);

    float acc[2][8][4];
#pragma unroll
    for (int i = 0; i < 2; i++)
#pragma unroll
        for (int j = 0; j < 8; j++)
#pragma unroll
            for (int q = 0; q < 4; q++) acc[i][j][q] = 0.f;

    const int nch = K >> 5;   // K / 32

    // prologue: chunk 0 -> buf 0
    {
        const uint32_t sb = tile;
#pragma unroll
        for (int j = 0; j < 4; j++) {
            float4 fa = *(const float4*)(Abase + j * 4);
            cvt_st(fa, sb + s_row + j * 8, sb + G_TILE + s_row + j * 8);
            float4 fb = *(const float4*)(Bbase + j * 4);
            cvt_st(fb, sb + 2 * G_TILE + s_row + j * 8,
                       sb + 3 * G_TILE + s_row + j * 8);
        }
    }
    __syncthreads();

    for (int i = 0; i < nch; i++) {
        const uint32_t cur = tile + (uint32_t)(i & 1) * G_STAGE_B;
        // load chunk i+1 into other buffer (overlaps with mma below)
        if (i + 1 < nch) {
            const uint32_t nb = tile + (uint32_t)((i + 1) & 1) * G_STAGE_B;
            const int k0 = (i + 1) << 5;
#pragma unroll
            for (int j = 0; j < 4; j++) {
                float4 fa = *(const float4*)(Abase + k0 + j * 4);
                cvt_st(fa, nb + s_row + j * 8, nb + G_TILE + s_row + j * 8);
                float4 fb = *(const float4*)(Bbase + k0 + j * 4);
                cvt_st(fb, nb + 2 * G_TILE + s_row + j * 8,
                           nb + 3 * G_TILE + s_row + j * 8);
            }
        }

        // compute chunk i: two k16 steps
#pragma unroll
        for (int ks = 0; ks < 2; ks++) {
            uint32_t ah[8], al[8];
            const uint32_t ka = cur + a_off + ks * 32;
            ldm4(ah,     ka);
            ldm4(ah + 4, ka + 16 * G_ROWB);
            ldm4(al,     ka + G_TILE);
            ldm4(al + 4, ka + G_TILE + 16 * G_ROWB);
#pragma unroll
            for (int g = 0; g < 4; g++) {
                uint32_t bh[4], bl[4];
                const uint32_t kb = cur + 2 * G_TILE + b_off + ks * 32 +
                                    g * (16 * G_ROWB);
                ldm4(bh, kb);
                ldm4(bl, kb + G_TILE);
#pragma unroll
                for (int ms = 0; ms < 2; ms++) {
                    mma16816(acc[ms][2 * g],     ah + 4 * ms, bh[0], bh[1]);
                    mma16816(acc[ms][2 * g + 1], ah + 4 * ms, bh[2], bh[3]);
                    mma16816(acc[ms][2 * g],     ah + 4 * ms, bl[0], bl[1]);
                    mma16816(acc[ms][2 * g + 1], ah + 4 * ms, bl[2], bl[3]);
                    mma16816(acc[ms][2 * g],     al + 4 * ms, bh[0], bh[1]);
                    mma16816(acc[ms][2 * g + 1], al + 4 * ms, bh[2], bh[3]);
                }
            }
        }
        __syncthreads();
    }

    // epilogue
    const int trow = lane >> 2;
    const int tcol = (lane & 3) * 2;
#pragma unroll
    for (int ms = 0; ms < 2; ms++) {
#pragma unroll
        for (int nf = 0; nf < 8; nf++) {
            const int r = bm + wm * 32 + ms * 16 + trow;
            const int c = bn + wn * 64 + nf * 8 + tcol;
            *(float2*)(C + (size_t)r * N + c) =
                make_float2(acc[ms][nf][0], acc[ms][nf][1]);
            *(float2*)(C + (size_t)(r + 8) * N + c) =
                make_float2(acc[ms][nf][2], acc[ms][nf][3]);
        }
    }
}

// ---------------- RoPE + head transpose ------------------------------------
__global__ __launch_bounds__(256) void rope_reorder(const float* __restrict__ cosp,
                                                    const float* __restrict__ sinp) {
    const int token = blockIdx.x;
    const int b = token / Tdim;
    const int t = token % Tdim;
    __shared__ float cs[HD], sn[HD];
    if (threadIdx.x < HD) {
        cs[threadIdx.x] = cosp[(size_t)token * HD + threadIdx.x];
        sn[threadIdx.x] = sinp[(size_t)token * HD + threadIdx.x];
    }
    __syncthreads();

    for (int p = threadIdx.x; p < NH * 32; p += 256) {
        const int hh = p >> 5;
        const int d  = p & 31;
        const size_t src = (size_t)token * (NH * HD) + hh * HD + d;
        float x1 = g_qt[src];
        float x2 = g_qt[src + 32];
        float c = cs[d], s = sn[d];
        const size_t base = ((size_t)(b * NH + hh) * Tdim + t) * HD;
        g_q[base + d]      = x1 * c - x2 * s;
        g_q[base + d + 32] = x2 * c + x1 * s;
    }
    for (int p = threadIdx.x; p < NKV * 32; p += 256) {
        const int hh = p >> 5;
        const int d  = p & 31;
        const size_t src = (size_t)token * (NKV * HD) + hh * HD + d;
        float x1 = g_kt[src];
        float x2 = g_kt[src + 32];
        float c = cs[d], s = sn[d];
        const size_t base = ((size_t)(b * NKV + hh) * Tdim + t) * HD;
        g_k[base + d]      = x1 * c - x2 * s;
        g_k[base + d + 32] = x2 * c + x1 * s;
    }
    for (int e = threadIdx.x; e < NKV * HD; e += 256) {
        const int hh = e >> 6;
        const int d  = e & 63;
        g_v[((size_t)(b * NKV + hh) * Tdim + t) * HD + d] =
            g_vt[(size_t)token * (NKV * HD) + e];
    }
}

// ---------------- Flash attention (fp32, causal, GQA) ----------------------
// Br=128, Bc=64. 256 threads: ty(0..15) x 8 rows, tx(0..15) x 4 cols.
// dyn smem floats: Qt[64][132] + Kt[64][68] + Ps[128][68] + Vs[64][64]
#define FA_SMEM_FLOATS (64 * 132 + 64 * 68 + 128 * 68 + 64 * 64)  // 25600
__global__ __launch_bounds__(256) void flash_attn2() {
    extern __shared__ float fsm[];
    float* Qt = fsm;                       // [d][r] stride 132
    float* Kt = fsm + 64 * 132;            // [d][c] stride 68
    float* Ps = Kt + 64 * 68;              // [r][c] stride 68
    float* Vs = Ps + 128 * 68;             // [c][d] stride 64

    const int qtile = (int)gridDim.x - 1 - (int)blockIdx.x;  // big tiles first
    const int bh = blockIdx.y;
    const int b = bh / NH;
    const int h = bh % NH;
    const int kvh = h / (NH / NKV);
    const int tid = threadIdx.x;
    const int tx = tid & 15;
    const int ty = tid >> 4;

    const float* qptr = g_q + ((size_t)bh * Tdim + qtile * 128) * HD;
    const float* kptr = g_k + ((size_t)(b * NKV + kvh) * Tdim) * HD;
    const float* vptr = g_v + ((size_t)(b * NKV + kvh) * Tdim) * HD;

#pragma unroll
    for (int j = 0; j < 8; j++) {
        const int lin = tid + j * 256;
        const int r = lin >> 4;
        const int d4 = (lin & 15) * 4;
        float4 v = *(const float4*)(qptr + (size_t)r * HD + d4);
        Qt[(d4 + 0) * 132 + r] = v.x * 0.125f;
        Qt[(d4 + 1) * 132 + r] = v.y * 0.125f;
        Qt[(d4 + 2) * 132 + r] = v.z * 0.125f;
        Qt[(d4 + 3) * 132 + r] = v.w * 0.125f;
    }

    float m[8], l[8], o[8][4];
#pragma unroll
    for (int i = 0; i < 8; i++) {
        m[i] = -1e30f; l[i] = 0.f;
#pragma unroll
        for (int j = 0; j < 4; j++) o[i][j] = 0.f;
    }
    __syncthreads();

    const int ktmax = 2 * qtile + 1;
    for (int kt = 0; kt <= ktmax; kt++) {
#pragma unroll
        for (int j = 0; j < 4; j++) {
            const int lin = tid + j * 256;
            const int r = lin >> 4;
            const int d4 = (lin & 15) * 4;
            float4 kv = *(const float4*)(kptr + (size_t)(kt * 64 + r) * HD + d4);
            Kt[(d4 + 0) * 68 + r] = kv.x;
            Kt[(d4 + 1) * 68 + r] = kv.y;
            Kt[(d4 + 2) * 68 + r] = kv.z;
            Kt[(d4 + 3) * 68 + r] = kv.w;
            float4 vv = *(const float4*)(vptr + (size_t)(kt * 64 + r) * HD + d4);
            *(float4*)(Vs + r * 64 + d4) = vv;
        }
        __syncthreads();

        float s[8][4];
#pragma unroll
        for (int i = 0; i < 8; i++)
#pragma unroll
            for (int j = 0; j < 4; j++) s[i][j] = 0.f;

#pragma unroll 8
        for (int d = 0; d < 64; d++) {
            float4 a0 = *(const float4*)(Qt + d * 132 + ty * 8);
            float4 a1 = *(const float4*)(Qt + d * 132 + ty * 8 + 4);
            float4 bv = *(const float4*)(Kt + d * 68 + tx * 4);
            float a[8] = {a0.x, a0.y, a0.z, a0.w, a1.x, a1.y, a1.z, a1.w};
#pragma unroll
            for (int i = 0; i < 8; i++) {
                s[i][0] = fmaf(a[i], bv.x, s[i][0]);
                s[i][1] = fmaf(a[i], bv.y, s[i][1]);
                s[i][2] = fmaf(a[i], bv.z, s[i][2]);
                s[i][3] = fmaf(a[i], bv.w, s[i][3]);
            }
        }

        if (kt >= 2 * qtile) {
#pragma unroll
            for (int i = 0; i < 8; i++) {
                const int qg = qtile * 128 + ty * 8 + i;
#pragma unroll
                for (int j = 0; j < 4; j++) {
                    if (kt * 64 + tx * 4 + j > qg) s[i][j] = -1e30f;
                }
            }
        }

#pragma unroll
        for (int i = 0; i < 8; i++) {
            float rm = fmaxf(fmaxf(s[i][0], s[i][1]), fmaxf(s[i][2], s[i][3]));
            rm = fmaxf(rm, __shfl_xor_sync(0xffffffffu, rm, 1));
            rm = fmaxf(rm, __shfl_xor_sync(0xffffffffu, rm, 2));
            rm = fmaxf(rm, __shfl_xor_sync(0xffffffffu, rm, 4));
            rm = fmaxf(rm, __shfl_xor_sync(0xffffffffu, rm, 8));
            float mn = fmaxf(m[i], rm);
            float alpha = __expf(m[i] - mn);
            m[i] = mn;
            float rs = 0.f;
#pragma unroll
            for (int j = 0; j < 4; j++) {
                s[i][j] = __expf(s[i][j] - mn);
                rs += s[i][j];
            }
            rs += __shfl_xor_sync(0xffffffffu, rs, 1);
            rs += __shfl_xor_sync(0xffffffffu, rs, 2);
            rs += __shfl_xor_sync(0xffffffffu, rs, 4);
            rs += __shfl_xor_sync(0xffffffffu, rs, 8);
            l[i] = l[i] * alpha + rs;
#pragma unroll
            for (int j = 0; j < 4; j++) o[i][j] *= alpha;
        }

#pragma unroll
        for (int i = 0; i < 8; i++)
            *(float4*)(Ps + (ty * 8 + i) * 68 + tx * 4) =
                make_float4(s[i][0], s[i][1], s[i][2], s[i][3]);
        __syncthreads();

#pragma unroll 8
        for (int c = 0; c < 64; c++) {
            float4 bv = *(const float4*)(Vs + c * 64 + tx * 4);
#pragma unroll
            for (int i = 0; i < 8; i++) {
                float a = Ps[(ty * 8 + i) * 68 + c];
                o[i][0] = fmaf(a, bv.x, o[i][0]);
                o[i][1] = fmaf(a, bv.y, o[i][1]);
                o[i][2] = fmaf(a, bv.z, o[i][2]);
                o[i][3] = fmaf(a, bv.w, o[i][3]);
            }
        }
        __syncthreads();
    }

#pragma unroll
    for (int i = 0; i < 8; i++) {
        const int row = qtile * 128 + ty * 8 + i;
        const float inv = 1.0f / l[i];
        *(float4*)(g_attn + ((size_t)b * Tdim + row) * (NH * HD) + h * HD + tx * 4) =
            make_float4(o[i][0] * inv, o[i][1] * inv, o[i][2] * inv, o[i][3] * inv);
    }
}

// ---------------- launch ----------------------------------------------------
extern "C" void kernel_launch(void* const* d_in, const int* in_sizes, int n_in,
                              void* d_out, int out_size) {
    const float* hidden = (const float*)d_in[0];
    const float* cosp   = (const float*)d_in[1];
    const float* sinp   = (const float*)d_in[2];
    const float* wq     = (const float*)d_in[3];
    const float* wk     = (const float*)d_in[4];
    const float* wv     = (const float*)d_in[5];
    const float* wo     = (const float*)d_in[6];
    float* out = (float*)d_out;

    float *qt, *kt, *vt, *attn;
    cudaGetSymbolAddress((void**)&qt,   g_qt);
    cudaGetSymbolAddress((void**)&kt,   g_kt);
    cudaGetSymbolAddress((void**)&vt,   g_vt);
    cudaGetSymbolAddress((void**)&attn, g_attn);

    cudaFuncSetAttribute(gemm_mma, cudaFuncAttributeMaxDynamicSharedMemorySize,
                         G_SMEM);
    const int fa_smem = FA_SMEM_FLOATS * sizeof(float);  // 102400 B
    cudaFuncSetAttribute(flash_attn2, cudaFuncAttributeMaxDynamicSharedMemorySize,
                         fa_smem);

    // QKV projections (mma.sync bf16, 3x split)
    gemm_mma<<<dim3(16, 32), 256, G_SMEM>>>(hidden, wq, qt, BT, NH * HD, HID);
    gemm_mma<<<dim3(4, 32),  256, G_SMEM>>>(hidden, wk, kt, BT, NKV * HD, HID);
    gemm_mma<<<dim3(4, 32),  256, G_SMEM>>>(hidden, wv, vt, BT, NKV * HD, HID);

    // RoPE + transpose
    rope_reorder<<<BT, 256>>>(cosp, sinp);

    // Flash attention (fp32)
    flash_attn2<<<dim3(Tdim / 128, Bdim * NH), 256, fa_smem>>>();

    // Output projection
    gemm_mma<<<dim3(16, 32), 256, G_SMEM>>>(attn, wo, out, BT, HID, HID);
}

// round 7
// speedup vs baseline: 1.7969x; 1.0047x over previous
#include <cuda_runtime.h>
#include <cstdint>
#include <math.h>

#define Bdim 2
#define Tdim 2048
#define HID 2048
#define NH 32
#define NKV 8
#define HD 64
#define BT (Bdim * Tdim)   // 4096

// ---------------- scratch (device globals; no allocations allowed) ----------
__device__ float g_qt[(size_t)BT * NH * HD];    // [4096, 2048] pre-rope Q
__device__ float g_kt[(size_t)BT * NKV * HD];   // [4096, 512]
__device__ float g_vt[(size_t)BT * NKV * HD];   // [4096, 512]
__device__ float g_q [(size_t)Bdim * NH  * Tdim * HD];  // [B,NH,T,HD]
__device__ float g_k [(size_t)Bdim * NKV * Tdim * HD];  // [B,NKV,T,HD]
__device__ float g_v [(size_t)Bdim * NKV * Tdim * HD];  // [B,NKV,T,HD]
__device__ float g_attn[(size_t)BT * NH * HD];  // [4096, 2048] attn output

// ======================= helpers ============================================
static __device__ __forceinline__ uint32_t smem_u32(const void* p) {
    uint32_t a;
    asm("{ .reg .u64 t; cvta.to.shared.u64 t, %1; cvt.u32.u64 %0, t; }"
        : "=r"(a) : "l"(p));
    return a;
}

static __device__ __forceinline__ void ldm4(uint32_t* r, uint32_t addr) {
    asm volatile("ldmatrix.sync.aligned.m8n8.x4.shared.b16 {%0,%1,%2,%3}, [%4];"
                 : "=r"(r[0]), "=r"(r[1]), "=r"(r[2]), "=r"(r[3]) : "r"(addr));
}

static __device__ __forceinline__ void mma16816(float* c, const uint32_t* a,
                                                uint32_t b0, uint32_t b1) {
    asm volatile("mma.sync.aligned.m16n8k16.row.col.f32.bf16.bf16.f32 "
                 "{%0,%1,%2,%3}, {%4,%5,%6,%7}, {%8,%9}, {%0,%1,%2,%3};"
                 : "+f"(c[0]), "+f"(c[1]), "+f"(c[2]), "+f"(c[3])
                 : "r"(a[0]), "r"(a[1]), "r"(a[2]), "r"(a[3]), "r"(b0), "r"(b1));
}

// float4 -> bf16 hi (truncate; exact) + bf16 lo (rounded residual); 8B stores.
static __device__ __forceinline__ void cvt_st(float4 f, uint32_t hi, uint32_t lo) {
    uint32_t xu = __float_as_uint(f.x), yu = __float_as_uint(f.y);
    uint32_t zu = __float_as_uint(f.z), wu = __float_as_uint(f.w);
    uint32_t h01 = __byte_perm(xu, yu, 0x7632);
    uint32_t h23 = __byte_perm(zu, wu, 0x7632);
    float lx = f.x - __uint_as_float(xu & 0xFFFF0000u);
    float ly = f.y - __uint_as_float(yu & 0xFFFF0000u);
    float lz = f.z - __uint_as_float(zu & 0xFFFF0000u);
    float lw = f.w - __uint_as_float(wu & 0xFFFF0000u);
    uint32_t l01, l23;
    asm("cvt.rn.satfinite.bf16x2.f32 %0, %1, %2;" : "=r"(l01) : "f"(ly), "f"(lx));
    asm("cvt.rn.satfinite.bf16x2.f32 %0, %1, %2;" : "=r"(l23) : "f"(lw), "f"(lz));
    asm volatile("st.shared.v2.b32 [%0], {%1, %2};" :: "r"(hi), "r"(h01), "r"(h23) : "memory");
    asm volatile("st.shared.v2.b32 [%0], {%1, %2};" :: "r"(lo), "r"(l01), "r"(l23) : "memory");
}

// =============== mma.sync GEMM: C[M,N] = A[M,K] * B[N,K]^T ==================
// 128x128 CTA tile, BK=32, 256 threads (8 warps = 4m x 2n, 32x64 warp tile).
// 3x bf16 split (AhBh + AhBl + AlBh), fp32 accum. Double-buffered smem.
// smem tile: bf16 [128 rows][32 cols], row stride 80 B (64 data + 16 pad).
#define G_ROWB 80
#define G_TILE 10240                  // 128 * 80 bytes
#define G_STAGE_B (4 * G_TILE)        // Ah, Al, Bh, Bl = 40960
#define G_SMEM (2 * G_STAGE_B + 128)  // 82048

__global__ __launch_bounds__(256, 2) void gemm_mma(const float* __restrict__ A,
                                                   const float* __restrict__ Bm,
                                                   float* __restrict__ C,
                                                   int M, int N, int K) {
    extern __shared__ char dsm[];
    const uint32_t tile = (smem_u32(dsm) + 127u) & ~127u;

    const int tid = threadIdx.x;
    const int wid = tid >> 5;
    const int lane = tid & 31;
    const int wm = wid & 3;           // 0..3 (m)
    const int wn = wid >> 2;          // 0..1 (n)
    const int bm = blockIdx.y * 128;
    const int bn = blockIdx.x * 128;

    // loader mapping: 2 threads per row, each 16 cols (4 float4)
    const int lrow = tid >> 1;
    const int lc16 = (tid & 1) * 16;
    const float* Abase = A + (size_t)(bm + lrow) * K + lc16;
    const float* Bbase = Bm + (size_t)(bn + lrow) * K + lc16;
    const uint32_t s_row = (uint32_t)(lrow * G_ROWB + lc16 * 2);

    // ldmatrix lane offsets (bytes)
    const int r8 = lane & 7, sub = lane >> 3;
    const uint32_t a_off = (uint32_t)((wm * 32 + r8 + (sub & 1) * 8) * G_ROWB +
                                      (sub >> 1) * 16);
    const uint32_t b_off = (uint32_t)((wn * 64 + r8 + (sub >> 1) * 8) * G_ROWB +
                                      (sub & 1) * 16);

    float acc[2][8][4];
#pragma unroll
    for (int i = 0; i < 2; i++)
#pragma unroll
        for (int j = 0; j < 8; j++)
#pragma unroll
            for (int q = 0; q < 4; q++) acc[i][j][q] = 0.f;

    const int nch = K >> 5;   // K / 32

    // prologue: chunk 0 -> buf 0
    {
        const uint32_t sb = tile;
#pragma unroll
        for (int j = 0; j < 4; j++) {
            float4 fa = *(const float4*)(Abase + j * 4);
            cvt_st(fa, sb + s_row + j * 8, sb + G_TILE + s_row + j * 8);
            float4 fb = *(const float4*)(Bbase + j * 4);
            cvt_st(fb, sb + 2 * G_TILE + s_row + j * 8,
                       sb + 3 * G_TILE + s_row + j * 8);
        }
    }
    __syncthreads();

    for (int i = 0; i < nch; i++) {
        const uint32_t cur = tile + (uint32_t)(i & 1) * G_STAGE_B;
        // load chunk i+1 into other buffer (overlaps with mma below)
        if (i + 1 < nch) {
            const uint32_t nb = tile + (uint32_t)((i + 1) & 1) * G_STAGE_B;
            const int k0 = (i + 1) << 5;
#pragma unroll
            for (int j = 0; j < 4; j++) {
                float4 fa = *(const float4*)(Abase + k0 + j * 4);
                cvt_st(fa, nb + s_row + j * 8, nb + G_TILE + s_row + j * 8);
                float4 fb = *(const float4*)(Bbase + k0 + j * 4);
                cvt_st(fb, nb + 2 * G_TILE + s_row + j * 8,
                           nb + 3 * G_TILE + s_row + j * 8);
            }
        }

        // compute chunk i: two k16 steps
#pragma unroll
        for (int ks = 0; ks < 2; ks++) {
            uint32_t ah[8], al[8];
            const uint32_t ka = cur + a_off + ks * 32;
            ldm4(ah,     ka);
            ldm4(ah + 4, ka + 16 * G_ROWB);
            ldm4(al,     ka + G_TILE);
            ldm4(al + 4, ka + G_TILE + 16 * G_ROWB);
#pragma unroll
            for (int g = 0; g < 4; g++) {
                uint32_t bh[4], bl[4];
                const uint32_t kb = cur + 2 * G_TILE + b_off + ks * 32 +
                                    g * (16 * G_ROWB);
                ldm4(bh, kb);
                ldm4(bl, kb + G_TILE);
#pragma unroll
                for (int ms = 0; ms < 2; ms++) {
                    mma16816(acc[ms][2 * g],     ah + 4 * ms, bh[0], bh[1]);
                    mma16816(acc[ms][2 * g + 1], ah + 4 * ms, bh[2], bh[3]);
                    mma16816(acc[ms][2 * g],     ah + 4 * ms, bl[0], bl[1]);
                    mma16816(acc[ms][2 * g + 1], ah + 4 * ms, bl[2], bl[3]);
                    mma16816(acc[ms][2 * g],     al + 4 * ms, bh[0], bh[1]);
                    mma16816(acc[ms][2 * g + 1], al + 4 * ms, bh[2], bh[3]);
                }
            }
        }
        __syncthreads();
    }

    // epilogue
    const int trow = lane >> 2;
    const int tcol = (lane & 3) * 2;
#pragma unroll
    for (int ms = 0; ms < 2; ms++) {
#pragma unroll
        for (int nf = 0; nf < 8; nf++) {
            const int r = bm + wm * 32 + ms * 16 + trow;
            const int c = bn + wn * 64 + nf * 8 + tcol;
            *(float2*)(C + (size_t)r * N + c) =
                make_float2(acc[ms][nf][0], acc[ms][nf][1]);
            *(float2*)(C + (size_t)(r + 8) * N + c) =
                make_float2(acc[ms][nf][2], acc[ms][nf][3]);
        }
    }
}

// ---------------- RoPE + head transpose ------------------------------------
__global__ __launch_bounds__(256) void rope_reorder(const float* __restrict__ cosp,
                                                    const float* __restrict__ sinp) {
    const int token = blockIdx.x;
    const int b = token / Tdim;
    const int t = token % Tdim;
    __shared__ float cs[HD], sn[HD];
    if (threadIdx.x < HD) {
        cs[threadIdx.x] = cosp[(size_t)token * HD + threadIdx.x];
        sn[threadIdx.x] = sinp[(size_t)token * HD + threadIdx.x];
    }
    __syncthreads();

    for (int p = threadIdx.x; p < NH * 32; p += 256) {
        const int hh = p >> 5;
        const int d  = p & 31;
        const size_t src = (size_t)token * (NH * HD) + hh * HD + d;
        float x1 = g_qt[src];
        float x2 = g_qt[src + 32];
        float c = cs[d], s = sn[d];
        const size_t base = ((size_t)(b * NH + hh) * Tdim + t) * HD;
        g_q[base + d]      = x1 * c - x2 * s;
        g_q[base + d + 32] = x2 * c + x1 * s;
    }
    for (int p = threadIdx.x; p < NKV * 32; p += 256) {
        const int hh = p >> 5;
        const int d  = p & 31;
        const size_t src = (size_t)token * (NKV * HD) + hh * HD + d;
        float x1 = g_kt[src];
        float x2 = g_kt[src + 32];
        float c = cs[d], s = sn[d];
        const size_t base = ((size_t)(b * NKV + hh) * Tdim + t) * HD;
        g_k[base + d]      = x1 * c - x2 * s;
        g_k[base + d + 32] = x2 * c + x1 * s;
    }
    for (int e = threadIdx.x; e < NKV * HD; e += 256) {
        const int hh = e >> 6;
        const int d  = e & 63;
        g_v[((size_t)(b * NKV + hh) * Tdim + t) * HD + d] =
            g_vt[(size_t)token * (NKV * HD) + e];
    }
}

// ---------------- Flash attention (fp32, causal, GQA) ----------------------
// Br=128, Bc=64. 256 threads: ty(0..15) x 8 rows, tx(0..15) x 4 cols.
// dyn smem floats: Qt[64][132] + Kt[64][68] + Ps[128][68] + Vs[64][64]
#define FA_SMEM_FLOATS (64 * 132 + 64 * 68 + 128 * 68 + 64 * 64)  // 25600
__global__ __launch_bounds__(256) void flash_attn2() {
    extern __shared__ float fsm[];
    float* Qt = fsm;                       // [d][r] stride 132
    float* Kt = fsm + 64 * 132;            // [d][c] stride 68
    float* Ps = Kt + 64 * 68;              // [r][c] stride 68
    float* Vs = Ps + 128 * 68;             // [c][d] stride 64

    const int qtile = (int)gridDim.x - 1 - (int)blockIdx.x;  // big tiles first
    const int bh = blockIdx.y;
    const int b = bh / NH;
    const int h = bh % NH;
    const int kvh = h / (NH / NKV);
    const int tid = threadIdx.x;
    const int tx = tid & 15;
    const int ty = tid >> 4;

    const float* qptr = g_q + ((size_t)bh * Tdim + qtile * 128) * HD;
    const float* kptr = g_k + ((size_t)(b * NKV + kvh) * Tdim) * HD;
    const float* vptr = g_v + ((size_t)(b * NKV + kvh) * Tdim) * HD;

#pragma unroll
    for (int j = 0; j < 8; j++) {
        const int lin = tid + j * 256;
        const int r = lin >> 4;
        const int d4 = (lin & 15) * 4;
        float4 v = *(const float4*)(qptr + (size_t)r * HD + d4);
        Qt[(d4 + 0) * 132 + r] = v.x * 0.125f;
        Qt[(d4 + 1) * 132 + r] = v.y * 0.125f;
        Qt[(d4 + 2) * 132 + r] = v.z * 0.125f;
        Qt[(d4 + 3) * 132 + r] = v.w * 0.125f;
    }

    float m[8], l[8], o[8][4];
#pragma unroll
    for (int i = 0; i < 8; i++) {
        m[i] = -1e30f; l[i] = 0.f;
#pragma unroll
        for (int j = 0; j < 4; j++) o[i][j] = 0.f;
    }
    __syncthreads();

    const int ktmax = 2 * qtile + 1;
    for (int kt = 0; kt <= ktmax; kt++) {
#pragma unroll
        for (int j = 0; j < 4; j++) {
            const int lin = tid + j * 256;
            const int r = lin >> 4;
            const int d4 = (lin & 15) * 4;
            float4 kv = *(const float4*)(kptr + (size_t)(kt * 64 + r) * HD + d4);
            Kt[(d4 + 0) * 68 + r] = kv.x;
            Kt[(d4 + 1) * 68 + r] = kv.y;
            Kt[(d4 + 2) * 68 + r] = kv.z;
            Kt[(d4 + 3) * 68 + r] = kv.w;
            float4 vv = *(const float4*)(vptr + (size_t)(kt * 64 + r) * HD + d4);
            *(float4*)(Vs + r * 64 + d4) = vv;
        }
        __syncthreads();

        float s[8][4];
#pragma unroll
        for (int i = 0; i < 8; i++)
#pragma unroll
            for (int j = 0; j < 4; j++) s[i][j] = 0.f;

#pragma unroll 8
        for (int d = 0; d < 64; d++) {
            float4 a0 = *(const float4*)(Qt + d * 132 + ty * 8);
            float4 a1 = *(const float4*)(Qt + d * 132 + ty * 8 + 4);
            float4 bv = *(const float4*)(Kt + d * 68 + tx * 4);
            float a[8] = {a0.x, a0.y, a0.z, a0.w, a1.x, a1.y, a1.z, a1.w};
#pragma unroll
            for (int i = 0; i < 8; i++) {
                s[i][0] = fmaf(a[i], bv.x, s[i][0]);
                s[i][1] = fmaf(a[i], bv.y, s[i][1]);
                s[i][2] = fmaf(a[i], bv.z, s[i][2]);
                s[i][3] = fmaf(a[i], bv.w, s[i][3]);
            }
        }

        if (kt >= 2 * qtile) {
#pragma unroll
            for (int i = 0; i < 8; i++) {
                const int qg = qtile * 128 + ty * 8 + i;
#pragma unroll
                for (int j = 0; j < 4; j++) {
                    if (kt * 64 + tx * 4 + j > qg) s[i][j] = -1e30f;
                }
            }
        }

#pragma unroll
        for (int i = 0; i < 8; i++) {
            float rm = fmaxf(fmaxf(s[i][0], s[i][1]), fmaxf(s[i][2], s[i][3]));
            rm = fmaxf(rm, __shfl_xor_sync(0xffffffffu, rm, 1));
            rm = fmaxf(rm, __shfl_xor_sync(0xffffffffu, rm, 2));
            rm = fmaxf(rm, __shfl_xor_sync(0xffffffffu, rm, 4));
            rm = fmaxf(rm, __shfl_xor_sync(0xffffffffu, rm, 8));
            float mn = fmaxf(m[i], rm);
            float alpha = __expf(m[i] - mn);
            m[i] = mn;
            float rs = 0.f;
#pragma unroll
            for (int j = 0; j < 4; j++) {
                s[i][j] = __expf(s[i][j] - mn);
                rs += s[i][j];
            }
            rs += __shfl_xor_sync(0xffffffffu, rs, 1);
            rs += __shfl_xor_sync(0xffffffffu, rs, 2);
            rs += __shfl_xor_sync(0xffffffffu, rs, 4);
            rs += __shfl_xor_sync(0xffffffffu, rs, 8);
            l[i] = l[i] * alpha + rs;
#pragma unroll
            for (int j = 0; j < 4; j++) o[i][j] *= alpha;
        }

#pragma unroll
        for (int i = 0; i < 8; i++)
            *(float4*)(Ps + (ty * 8 + i) * 68 + tx * 4) =
                make_float4(s[i][0], s[i][1], s[i][2], s[i][3]);
        __syncthreads();

#pragma unroll 8
        for (int c = 0; c < 64; c++) {
            float4 bv = *(const float4*)(Vs + c * 64 + tx * 4);
#pragma unroll
            for (int i = 0; i < 8; i++) {
                float a = Ps[(ty * 8 + i) * 68 + c];
                o[i][0] = fmaf(a, bv.x, o[i][0]);
                o[i][1] = fmaf(a, bv.y, o[i][1]);
                o[i][2] = fmaf(a, bv.z, o[i][2]);
                o[i][3] = fmaf(a, bv.w, o[i][3]);
            }
        }
        __syncthreads();
    }

#pragma unroll
    for (int i = 0; i < 8; i++) {
        const int row = qtile * 128 + ty * 8 + i;
        const float inv = 1.0f / l[i];
        *(float4*)(g_attn + ((size_t)b * Tdim + row) * (NH * HD) + h * HD + tx * 4) =
            make_float4(o[i][0] * inv, o[i][1] * inv, o[i][2] * inv, o[i][3] * inv);
    }
}

// ---------------- launch ----------------------------------------------------
extern "C" void kernel_launch(void* const* d_in, const int* in_sizes, int n_in,
                              void* d_out, int out_size) {
    const float* hidden = (const float*)d_in[0];
    const float* cosp   = (const float*)d_in[1];
    const float* sinp   = (const float*)d_in[2];
    const float* wq     = (const float*)d_in[3];
    const float* wk     = (const float*)d_in[4];
    const float* wv     = (const float*)d_in[5];
    const float* wo     = (const float*)d_in[6];
    float* out = (float*)d_out;

    float *qt, *kt, *vt, *attn;
    cudaGetSymbolAddress((void**)&qt,   g_qt);
    cudaGetSymbolAddress((void**)&kt,   g_kt);
    cudaGetSymbolAddress((void**)&vt,   g_vt);
    cudaGetSymbolAddress((void**)&attn, g_attn);

    cudaFuncSetAttribute(gemm_mma, cudaFuncAttributeMaxDynamicSharedMemorySize,
                         G_SMEM);
    const int fa_smem = FA_SMEM_FLOATS * sizeof(float);  // 102400 B
    cudaFuncSetAttribute(flash_attn2, cudaFuncAttributeMaxDynamicSharedMemorySize,
                         fa_smem);

    // QKV projections (mma.sync bf16, 3x split)
    gemm_mma<<<dim3(16, 32), 256, G_SMEM>>>(hidden, wq, qt, BT, NH * HD, HID);
    gemm_mma<<<dim3(4, 32),  256, G_SMEM>>>(hidden, wk, kt, BT, NKV * HD, HID);
    gemm_mma<<<dim3(4, 32),  256, G_SMEM>>>(hidden, wv, vt, BT, NKV * HD, HID);

    // RoPE + transpose
    rope_reorder<<<BT, 256>>>(cosp, sinp);

    // Flash attention (fp32)
    flash_attn2<<<dim3(Tdim / 128, Bdim * NH), 256, fa_smem>>>();

    // Output projection
    gemm_mma<<<dim3(16, 32), 256, G_SMEM>>>(attn, wo, out, BT, HID, HID);
}

// round 8
// speedup vs baseline: 2.6620x; 1.4814x over previous
#include <cuda_runtime.h>
#include <cstdint>
#include <math.h>

#define Bdim 2
#define Tdim 2048
#define HID 2048
#define NH 32
#define NKV 8
#define HD 64
#define BT (Bdim * Tdim)   // 4096

// ---------------- scratch (device globals; no allocations allowed) ----------
__device__ float g_qt[(size_t)BT * NH * HD];    // [4096, 2048] pre-rope Q
__device__ float g_kt[(size_t)BT * NKV * HD];   // [4096, 512]
__device__ float g_vt[(size_t)BT * NKV * HD];   // [4096, 512]
// split bf16 (stored as ushort bit patterns), hi = truncation, lo = residual
__device__ __align__(16) unsigned short g_qh[(size_t)Bdim * NH  * Tdim * HD];
__device__ __align__(16) unsigned short g_ql[(size_t)Bdim * NH  * Tdim * HD];
__device__ __align__(16) unsigned short g_kh[(size_t)Bdim * NKV * Tdim * HD];
__device__ __align__(16) unsigned short g_kl[(size_t)Bdim * NKV * Tdim * HD];
__device__ __align__(16) unsigned short g_vh[(size_t)Bdim * NKV * Tdim * HD];
__device__ __align__(16) unsigned short g_vl[(size_t)Bdim * NKV * Tdim * HD];
__device__ float g_attn[(size_t)BT * NH * HD];  // [4096, 2048] attn output

// ======================= helpers ============================================
static __device__ __forceinline__ uint32_t smem_u32(const void* p) {
    uint32_t a;
    asm("{ .reg .u64 t; cvta.to.shared.u64 t, %1; cvt.u32.u64 %0, t; }"
        : "=r"(a) : "l"(p));
    return a;
}

static __device__ __forceinline__ void ldm4(uint32_t* r, uint32_t addr) {
    asm volatile("ldmatrix.sync.aligned.m8n8.x4.shared.b16 {%0,%1,%2,%3}, [%4];"
                 : "=r"(r[0]), "=r"(r[1]), "=r"(r[2]), "=r"(r[3]) : "r"(addr));
}

static __device__ __forceinline__ void ldm4t(uint32_t* r, uint32_t addr) {
    asm volatile("ldmatrix.sync.aligned.m8n8.x4.trans.shared.b16 {%0,%1,%2,%3}, [%4];"
                 : "=r"(r[0]), "=r"(r[1]), "=r"(r[2]), "=r"(r[3]) : "r"(addr));
}

static __device__ __forceinline__ void mma16816(float* c, const uint32_t* a,
                                                uint32_t b0, uint32_t b1) {
    asm volatile("mma.sync.aligned.m16n8k16.row.col.f32.bf16.bf16.f32 "
                 "{%0,%1,%2,%3}, {%4,%5,%6,%7}, {%8,%9}, {%0,%1,%2,%3};"
                 : "+f"(c[0]), "+f"(c[1]), "+f"(c[2]), "+f"(c[3])
                 : "r"(a[0]), "r"(a[1]), "r"(a[2]), "r"(a[3]), "r"(b0), "r"(b1));
}

// pack two floats as truncated-bf16x2 (low = a, high = b)
static __device__ __forceinline__ uint32_t pack_hi(float a, float b) {
    return __byte_perm(__float_as_uint(a), __float_as_uint(b), 0x7632);
}
// pack residuals (rounded) as bf16x2 (low = a - trunc(a), high = b - trunc(b))
static __device__ __forceinline__ uint32_t pack_lo(float a, float b) {
    float ra = a - __uint_as_float(__float_as_uint(a) & 0xFFFF0000u);
    float rb = b - __uint_as_float(__float_as_uint(b) & 0xFFFF0000u);
    uint32_t r;
    asm("cvt.rn.satfinite.bf16x2.f32 %0, %1, %2;" : "=r"(r) : "f"(rb), "f"(ra));
    return r;
}

// float4 -> bf16 hi + bf16 lo, 8B stores to smem (for GEMM staging).
static __device__ __forceinline__ void cvt_st(float4 f, uint32_t hi, uint32_t lo) {
    uint32_t h01 = pack_hi(f.x, f.y);
    uint32_t h23 = pack_hi(f.z, f.w);
    uint32_t l01 = pack_lo(f.x, f.y);
    uint32_t l23 = pack_lo(f.z, f.w);
    asm volatile("st.shared.v2.b32 [%0], {%1, %2};" :: "r"(hi), "r"(h01), "r"(h23) : "memory");
    asm volatile("st.shared.v2.b32 [%0], {%1, %2};" :: "r"(lo), "r"(l01), "r"(l23) : "memory");
}

// scalar split for rope stage
static __device__ __forceinline__ void split_store(float x, unsigned short* ph,
                                                   unsigned short* pl) {
    uint32_t u = __float_as_uint(x);
    *ph = (unsigned short)(u >> 16);
    float lo = x - __uint_as_float(u & 0xFFFF0000u);
    unsigned short ls;
    asm("cvt.rn.satfinite.bf16.f32 %0, %1;" : "=h"(ls) : "f"(lo));
    *pl = ls;
}

// =============== mma.sync GEMM: C[M,N] = A[M,K] * B[N,K]^T ==================
// (unchanged from R7 — verified correct)
#define G_ROWB 80
#define G_TILE 10240
#define G_STAGE_B (4 * G_TILE)
#define G_SMEM (2 * G_STAGE_B + 128)

__global__ __launch_bounds__(256, 2) void gemm_mma(const float* __restrict__ A,
                                                   const float* __restrict__ Bm,
                                                   float* __restrict__ C,
                                                   int M, int N, int K) {
    extern __shared__ char dsm[];
    const uint32_t tile = (smem_u32(dsm) + 127u) & ~127u;

    const int tid = threadIdx.x;
    const int wid = tid >> 5;
    const int lane = tid & 31;
    const int wm = wid & 3;
    const int wn = wid >> 2;
    const int bm = blockIdx.y * 128;
    const int bn = blockIdx.x * 128;

    const int lrow = tid >> 1;
    const int lc16 = (tid & 1) * 16;
    const float* Abase = A + (size_t)(bm + lrow) * K + lc16;
    const float* Bbase = Bm + (size_t)(bn + lrow) * K + lc16;
    const uint32_t s_row = (uint32_t)(lrow * G_ROWB + lc16 * 2);

    const int r8 = lane & 7, sub = lane >> 3;
    const uint32_t a_off = (uint32_t)((wm * 32 + r8 + (sub & 1) * 8) * G_ROWB +
                                      (sub >> 1) * 16);
    const uint32_t b_off = (uint32_t)((wn * 64 + r8 + (sub >> 1) * 8) * G_ROWB +
                                      (sub & 1) * 16);

    float acc[2][8][4];
#pragma unroll
    for (int i = 0; i < 2; i++)
#pragma unroll
        for (int j = 0; j < 8; j++)
#pragma unroll
            for (int q = 0; q < 4; q++) acc[i][j][q] = 0.f;

    const int nch = K >> 5;

    {
        const uint32_t sb = tile;
#pragma unroll
        for (int j = 0; j < 4; j++) {
            float4 fa = *(const float4*)(Abase + j * 4);
            cvt_st(fa, sb + s_row + j * 8, sb + G_TILE + s_row + j * 8);
            float4 fb = *(const float4*)(Bbase + j * 4);
            cvt_st(fb, sb + 2 * G_TILE + s_row + j * 8,
                       sb + 3 * G_TILE + s_row + j * 8);
        }
    }
    __syncthreads();

    for (int i = 0; i < nch; i++) {
        const uint32_t cur = tile + (uint32_t)(i & 1) * G_STAGE_B;
        if (i + 1 < nch) {
            const uint32_t nb = tile + (uint32_t)((i + 1) & 1) * G_STAGE_B;
            const int k0 = (i + 1) << 5;
#pragma unroll
            for (int j = 0; j < 4; j++) {
                float4 fa = *(const float4*)(Abase + k0 + j * 4);
                cvt_st(fa, nb + s_row + j * 8, nb + G_TILE + s_row + j * 8);
                float4 fb = *(const float4*)(Bbase + k0 + j * 4);
                cvt_st(fb, nb + 2 * G_TILE + s_row + j * 8,
                           nb + 3 * G_TILE + s_row + j * 8);
            }
        }

#pragma unroll
        for (int ks = 0; ks < 2; ks++) {
            uint32_t ah[8], al[8];
            const uint32_t ka = cur + a_off + ks * 32;
            ldm4(ah,     ka);
            ldm4(ah + 4, ka + 16 * G_ROWB);
            ldm4(al,     ka + G_TILE);
            ldm4(al + 4, ka + G_TILE + 16 * G_ROWB);
#pragma unroll
            for (int g = 0; g < 4; g++) {
                uint32_t bh[4], bl[4];
                const uint32_t kb = cur + 2 * G_TILE + b_off + ks * 32 +
                                    g * (16 * G_ROWB);
                ldm4(bh, kb);
                ldm4(bl, kb + G_TILE);
#pragma unroll
                for (int ms = 0; ms < 2; ms++) {
                    mma16816(acc[ms][2 * g],     ah + 4 * ms, bh[0], bh[1]);
                    mma16816(acc[ms][2 * g + 1], ah + 4 * ms, bh[2], bh[3]);
                    mma16816(acc[ms][2 * g],     ah + 4 * ms, bl[0], bl[1]);
                    mma16816(acc[ms][2 * g + 1], ah + 4 * ms, bl[2], bl[3]);
                    mma16816(acc[ms][2 * g],     al + 4 * ms, bh[0], bh[1]);
                    mma16816(acc[ms][2 * g + 1], al + 4 * ms, bh[2], bh[3]);
                }
            }
        }
        __syncthreads();
    }

    const int trow = lane >> 2;
    const int tcol = (lane & 3) * 2;
#pragma unroll
    for (int ms = 0; ms < 2; ms++) {
#pragma unroll
        for (int nf = 0; nf < 8; nf++) {
            const int r = bm + wm * 32 + ms * 16 + trow;
            const int c = bn + wn * 64 + nf * 8 + tcol;
            *(float2*)(C + (size_t)r * N + c) =
                make_float2(acc[ms][nf][0], acc[ms][nf][1]);
            *(float2*)(C + (size_t)(r + 8) * N + c) =
                make_float2(acc[ms][nf][2], acc[ms][nf][3]);
        }
    }
}

// ---------------- RoPE + head transpose + bf16 split ------------------------
__global__ __launch_bounds__(256) void rope_split(const float* __restrict__ cosp,
                                                  const float* __restrict__ sinp) {
    const int token = blockIdx.x;
    const int b = token / Tdim;
    const int t = token % Tdim;
    __shared__ float cs[HD], sn[HD];
    if (threadIdx.x < HD) {
        cs[threadIdx.x] = cosp[(size_t)token * HD + threadIdx.x];
        sn[threadIdx.x] = sinp[(size_t)token * HD + threadIdx.x];
    }
    __syncthreads();

    // Q: rope + scale by 0.125 + split
    for (int p = threadIdx.x; p < NH * 32; p += 256) {
        const int hh = p >> 5;
        const int d  = p & 31;
        const size_t src = (size_t)token * (NH * HD) + hh * HD + d;
        float x1 = g_qt[src];
        float x2 = g_qt[src + 32];
        float c = cs[d], s = sn[d];
        const size_t base = ((size_t)(b * NH + hh) * Tdim + t) * HD;
        float y1 = (x1 * c - x2 * s) * 0.125f;
        float y2 = (x2 * c + x1 * s) * 0.125f;
        split_store(y1, &g_qh[base + d],      &g_ql[base + d]);
        split_store(y2, &g_qh[base + d + 32], &g_ql[base + d + 32]);
    }
    // K: rope + split
    for (int p = threadIdx.x; p < NKV * 32; p += 256) {
        const int hh = p >> 5;
        const int d  = p & 31;
        const size_t src = (size_t)token * (NKV * HD) + hh * HD + d;
        float x1 = g_kt[src];
        float x2 = g_kt[src + 32];
        float c = cs[d], s = sn[d];
        const size_t base = ((size_t)(b * NKV + hh) * Tdim + t) * HD;
        float y1 = x1 * c - x2 * s;
        float y2 = x2 * c + x1 * s;
        split_store(y1, &g_kh[base + d],      &g_kl[base + d]);
        split_store(y2, &g_kh[base + d + 32], &g_kl[base + d + 32]);
    }
    // V: transpose + split
    for (int e = threadIdx.x; e < NKV * HD; e += 256) {
        const int hh = e >> 6;
        const int d  = e & 63;
        float v = g_vt[(size_t)token * (NKV * HD) + e];
        const size_t base = ((size_t)(b * NKV + hh) * Tdim + t) * HD;
        split_store(v, &g_vh[base + d], &g_vl[base + d]);
    }
}

// ---------------- Flash attention (tensor cores, causal, GQA) ---------------
// Br=64, Bc=64, 128 threads (4 warps; warp w owns rows w*16..w*16+15).
// smem: Qh,Ql,Kh,Kl,Vh,Vl tiles, each 64 rows x 144B (72 ushort) = 9216 B.
#define FB 144
#define FT 9216
#define FA_SMEM (6 * FT)   // 55296

__global__ __launch_bounds__(128, 3) void flash_mma() {
    extern __shared__ unsigned short fsm[];
    const uint32_t s0 = smem_u32(fsm);
    const uint32_t sQh = s0, sQl = s0 + FT, sKh = s0 + 2 * FT, sKl = s0 + 3 * FT;
    const uint32_t sVh = s0 + 4 * FT, sVl = s0 + 5 * FT;

    const int tid = threadIdx.x;
    const int lane = tid & 31;
    const int w = tid >> 5;
    const int qtile = (int)gridDim.x - 1 - (int)blockIdx.x;  // big first
    const int bh = blockIdx.y;
    const int b = bh / NH;
    const int h = bh % NH;
    const int kvh = h / (NH / NKV);

    const unsigned short* qhp = g_qh + ((size_t)bh * Tdim + qtile * 64) * HD;
    const unsigned short* qlp = g_ql + ((size_t)bh * Tdim + qtile * 64) * HD;
    const size_t kvbase = (size_t)(b * NKV + kvh) * Tdim * HD;

    // stage Q tiles (64x64 bf16 each): 512 uint4 per tile / 128 thr = 4 each
    const int lrow = tid >> 1;               // not used for Q; use idx mapping
#pragma unroll
    for (int j = 0; j < 4; j++) {
        const int idx = tid + j * 128;
        const int row = idx >> 3;
        const int c = idx & 7;
        uint4 vh = *(const uint4*)(qhp + row * HD + c * 8);
        uint4 vl = *(const uint4*)(qlp + row * HD + c * 8);
        *(uint4*)(fsm + row * 72 + c * 8) = vh;
        *(uint4*)(fsm + 72 * 64 + row * 72 + c * 8) = vl;
    }

    // fragment offsets
    const int r8 = lane & 7, sub = lane >> 3;
    const uint32_t a_off = (uint32_t)((w * 16 + r8 + ((sub & 1) << 3)) * FB +
                                      ((sub >> 1) << 4));
    const uint32_t b_off = (uint32_t)((r8 + ((sub >> 1) << 3)) * FB +
                                      ((sub & 1) << 4));
    const uint32_t v_off = (uint32_t)(((lane & 8) + (lane & 7)) * FB +
                                      (lane >> 4) * 16);

    float m0 = -1e30f, m1 = -1e30f, l0 = 0.f, l1 = 0.f;
    float o[8][4];
#pragma unroll
    for (int t = 0; t < 8; t++)
#pragma unroll
        for (int e = 0; e < 4; e++) o[t][e] = 0.f;

    for (int kt = 0; kt <= qtile; kt++) {
        // global loads into regs (overlap with previous compute)
        uint4 rkh[4], rkl[4], rvh[4], rvl[4];
        const unsigned short* kh = g_kh + kvbase + (size_t)kt * 64 * HD;
        const unsigned short* kl = g_kl + kvbase + (size_t)kt * 64 * HD;
        const unsigned short* vh = g_vh + kvbase + (size_t)kt * 64 * HD;
        const unsigned short* vl = g_vl + kvbase + (size_t)kt * 64 * HD;
#pragma unroll
        for (int j = 0; j < 4; j++) {
            const int idx = tid + j * 128;
            const int off = (idx >> 3) * HD + (idx & 7) * 8;
            rkh[j] = *(const uint4*)(kh + off);
            rkl[j] = *(const uint4*)(kl + off);
            rvh[j] = *(const uint4*)(vh + off);
            rvl[j] = *(const uint4*)(vl + off);
        }
        __syncthreads();   // previous compute done (and Q staging on iter 0)
#pragma unroll
        for (int j = 0; j < 4; j++) {
            const int idx = tid + j * 128;
            const int so = (idx >> 3) * 72 + (idx & 7) * 8;
            *(uint4*)(fsm + 2 * 64 * 72 + so) = rkh[j];
            *(uint4*)(fsm + 3 * 64 * 72 + so) = rkl[j];
            *(uint4*)(fsm + 4 * 64 * 72 + so) = rvh[j];
            *(uint4*)(fsm + 5 * 64 * 72 + so) = rvl[j];
        }
        __syncthreads();

        // --- S = Q K^T (3x split), fp32 accum ---
        float sa[8][4];
#pragma unroll
        for (int t = 0; t < 8; t++)
#pragma unroll
            for (int e = 0; e < 4; e++) sa[t][e] = 0.f;

#pragma unroll
        for (int ks = 0; ks < 4; ks++) {
            uint32_t aqh[4], aql[4];
            ldm4(aqh, sQh + a_off + ks * 32);
            ldm4(aql, sQl + a_off + ks * 32);
#pragma unroll
            for (int g = 0; g < 4; g++) {
                uint32_t kbh[4], kbl[4];
                const uint32_t kb = sKh + b_off + ks * 32 + g * (16 * FB);
                ldm4(kbh, kb);
                ldm4(kbl, kb + FT);
                mma16816(sa[2 * g],     aqh, kbh[0], kbh[1]);
                mma16816(sa[2 * g + 1], aqh, kbh[2], kbh[3]);
                mma16816(sa[2 * g],     aqh, kbl[0], kbl[1]);
                mma16816(sa[2 * g + 1], aqh, kbl[2], kbl[3]);
                mma16816(sa[2 * g],     aql, kbh[0], kbh[1]);
                mma16816(sa[2 * g + 1], aql, kbh[2], kbh[3]);
            }
        }

        // --- causal mask on the diagonal tile ---
        if (kt == qtile) {
            const int row0 = w * 16 + (lane >> 2);
            const int colb = (lane & 3) * 2;
#pragma unroll
            for (int t = 0; t < 8; t++) {
                const int c0 = t * 8 + colb;
                if (c0 > row0)         sa[t][0] = -1e30f;
                if (c0 + 1 > row0)     sa[t][1] = -1e30f;
                if (c0 > row0 + 8)     sa[t][2] = -1e30f;
                if (c0 + 1 > row0 + 8) sa[t][3] = -1e30f;
            }
        }

        // --- online softmax (rows lane>>2 and +8) ---
        float rm0 = -1e30f, rm1 = -1e30f;
#pragma unroll
        for (int t = 0; t < 8; t++) {
            rm0 = fmaxf(rm0, fmaxf(sa[t][0], sa[t][1]));
            rm1 = fmaxf(rm1, fmaxf(sa[t][2], sa[t][3]));
        }
        rm0 = fmaxf(rm0, __shfl_xor_sync(0xffffffffu, rm0, 1));
        rm0 = fmaxf(rm0, __shfl_xor_sync(0xffffffffu, rm0, 2));
        rm1 = fmaxf(rm1, __shfl_xor_sync(0xffffffffu, rm1, 1));
        rm1 = fmaxf(rm1, __shfl_xor_sync(0xffffffffu, rm1, 2));
        const float mn0 = fmaxf(m0, rm0);
        const float mn1 = fmaxf(m1, rm1);
        const float al0 = __expf(m0 - mn0);
        const float al1 = __expf(m1 - mn1);
        m0 = mn0; m1 = mn1;
        float rs0 = 0.f, rs1 = 0.f;
#pragma unroll
        for (int t = 0; t < 8; t++) {
            sa[t][0] = __expf(sa[t][0] - mn0);
            sa[t][1] = __expf(sa[t][1] - mn0);
            sa[t][2] = __expf(sa[t][2] - mn1);
            sa[t][3] = __expf(sa[t][3] - mn1);
            rs0 += sa[t][0] + sa[t][1];
            rs1 += sa[t][2] + sa[t][3];
        }
        rs0 += __shfl_xor_sync(0xffffffffu, rs0, 1);
        rs0 += __shfl_xor_sync(0xffffffffu, rs0, 2);
        rs1 += __shfl_xor_sync(0xffffffffu, rs1, 1);
        rs1 += __shfl_xor_sync(0xffffffffu, rs1, 2);
        l0 = l0 * al0 + rs0;
        l1 = l1 * al1 + rs1;
#pragma unroll
        for (int t = 0; t < 8; t++) {
            o[t][0] *= al0; o[t][1] *= al0;
            o[t][2] *= al1; o[t][3] *= al1;
        }

        // --- repack P into A fragments (hi + lo split), register-only ---
        uint32_t ph[4][4], pl[4][4];
#pragma unroll
        for (int kc = 0; kc < 4; kc++) {
            const int t0 = 2 * kc, t1 = 2 * kc + 1;
            ph[kc][0] = pack_hi(sa[t0][0], sa[t0][1]);
            ph[kc][1] = pack_hi(sa[t0][2], sa[t0][3]);
            ph[kc][2] = pack_hi(sa[t1][0], sa[t1][1]);
            ph[kc][3] = pack_hi(sa[t1][2], sa[t1][3]);
            pl[kc][0] = pack_lo(sa[t0][0], sa[t0][1]);
            pl[kc][1] = pack_lo(sa[t0][2], sa[t0][3]);
            pl[kc][2] = pack_lo(sa[t1][0], sa[t1][1]);
            pl[kc][3] = pack_lo(sa[t1][2], sa[t1][3]);
        }

        // --- O += P V (3x split) ---
#pragma unroll
        for (int kc = 0; kc < 4; kc++) {
#pragma unroll
            for (int tp = 0; tp < 4; tp++) {
                uint32_t vbh[4], vbl[4];
                const uint32_t va = sVh + v_off + kc * (16 * FB) + tp * 32;
                ldm4t(vbh, va);
                ldm4t(vbl, va + FT);
                mma16816(o[2 * tp],     ph[kc], vbh[0], vbh[1]);
                mma16816(o[2 * tp + 1], ph[kc], vbh[2], vbh[3]);
                mma16816(o[2 * tp],     ph[kc], vbl[0], vbl[1]);
                mma16816(o[2 * tp + 1], ph[kc], vbl[2], vbl[3]);
                mma16816(o[2 * tp],     pl[kc], vbh[0], vbh[1]);
                mma16816(o[2 * tp + 1], pl[kc], vbh[2], vbh[3]);
            }
        }
    }

    // epilogue
    const float inv0 = 1.0f / l0;
    const float inv1 = 1.0f / l1;
    const int row0 = qtile * 64 + w * 16 + (lane >> 2);
    const int colb = (lane & 3) * 2;
#pragma unroll
    for (int t = 0; t < 8; t++) {
        const int c = h * HD + t * 8 + colb;
        *(float2*)(g_attn + ((size_t)b * Tdim + row0) * (NH * HD) + c) =
            make_float2(o[t][0] * inv0, o[t][1] * inv0);
        *(float2*)(g_attn + ((size_t)b * Tdim + row0 + 8) * (NH * HD) + c) =
            make_float2(o[t][2] * inv1, o[t][3] * inv1);
    }
    (void)lrow;
}

// ---------------- launch ----------------------------------------------------
extern "C" void kernel_launch(void* const* d_in, const int* in_sizes, int n_in,
                              void* d_out, int out_size) {
    const float* hidden = (const float*)d_in[0];
    const float* cosp   = (const float*)d_in[1];
    const float* sinp   = (const float*)d_in[2];
    const float* wq     = (const float*)d_in[3];
    const float* wk     = (const float*)d_in[4];
    const float* wv     = (const float*)d_in[5];
    const float* wo     = (const float*)d_in[6];
    float* out = (float*)d_out;

    float *qt, *kt, *vt, *attn;
    cudaGetSymbolAddress((void**)&qt,   g_qt);
    cudaGetSymbolAddress((void**)&kt,   g_kt);
    cudaGetSymbolAddress((void**)&vt,   g_vt);
    cudaGetSymbolAddress((void**)&attn, g_attn);

    cudaFuncSetAttribute(gemm_mma, cudaFuncAttributeMaxDynamicSharedMemorySize,
                         G_SMEM);
    cudaFuncSetAttribute(flash_mma, cudaFuncAttributeMaxDynamicSharedMemorySize,
                         FA_SMEM);

    // QKV projections (mma.sync bf16, 3x split)
    gemm_mma<<<dim3(16, 32), 256, G_SMEM>>>(hidden, wq, qt, BT, NH * HD, HID);
    gemm_mma<<<dim3(4, 32),  256, G_SMEM>>>(hidden, wk, kt, BT, NKV * HD, HID);
    gemm_mma<<<dim3(4, 32),  256, G_SMEM>>>(hidden, wv, vt, BT, NKV * HD, HID);

    // RoPE + transpose + bf16 split
    rope_split<<<BT, 256>>>(cosp, sinp);

    // Flash attention (tensor cores)
    flash_mma<<<dim3(Tdim / 64, Bdim * NH), 128, FA_SMEM>>>();

    // Output projection
    gemm_mma<<<dim3(16, 32), 256, G_SMEM>>>(attn, wo, out, BT, HID, HID);
}

// round 9
// speedup vs baseline: 2.9132x; 1.0944x over previous
#include <cuda_runtime.h>
#include <cstdint>
#include <math.h>

#define Bdim 2
#define Tdim 2048
#define HID 2048
#define NH 32
#define NKV 8
#define HD 64
#define BT (Bdim * Tdim)   // 4096

typedef unsigned short ushort_t;

// ---------------- scratch (device globals; no allocations allowed) ----------
__device__ float g_qt[(size_t)BT * NH * HD];    // pre-rope Q (fp32 GEMM out)
__device__ float g_kt[(size_t)BT * NKV * HD];
__device__ float g_vt[(size_t)BT * NKV * HD];
// pre-split GEMM inputs (bf16 hi = truncation, lo = residual)
__device__ __align__(16) ushort_t g_hh[(size_t)BT * HID];
__device__ __align__(16) ushort_t g_hl[(size_t)BT * HID];
__device__ __align__(16) ushort_t g_wqh[(size_t)NH * HD * HID];
__device__ __align__(16) ushort_t g_wql[(size_t)NH * HD * HID];
__device__ __align__(16) ushort_t g_wkh[(size_t)NKV * HD * HID];
__device__ __align__(16) ushort_t g_wkl[(size_t)NKV * HD * HID];
__device__ __align__(16) ushort_t g_wvh[(size_t)NKV * HD * HID];
__device__ __align__(16) ushort_t g_wvl[(size_t)NKV * HD * HID];
__device__ __align__(16) ushort_t g_woh[(size_t)HID * NH * HD];
__device__ __align__(16) ushort_t g_wol[(size_t)HID * NH * HD];
// roped / reordered split tensors for attention
__device__ __align__(16) ushort_t g_qh[(size_t)Bdim * NH  * Tdim * HD];
__device__ __align__(16) ushort_t g_ql[(size_t)Bdim * NH  * Tdim * HD];
__device__ __align__(16) ushort_t g_kh[(size_t)Bdim * NKV * Tdim * HD];
__device__ __align__(16) ushort_t g_kl[(size_t)Bdim * NKV * Tdim * HD];
__device__ __align__(16) ushort_t g_vh[(size_t)Bdim * NKV * Tdim * HD];
__device__ __align__(16) ushort_t g_vl[(size_t)Bdim * NKV * Tdim * HD];
// attention output, pre-split for the O projection
__device__ __align__(16) ushort_t g_oh[(size_t)BT * NH * HD];
__device__ __align__(16) ushort_t g_ol[(size_t)BT * NH * HD];

// ======================= helpers ============================================
static __device__ __forceinline__ uint32_t smem_u32(const void* p) {
    uint32_t a;
    asm("{ .reg .u64 t; cvta.to.shared.u64 t, %1; cvt.u32.u64 %0, t; }"
        : "=r"(a) : "l"(p));
    return a;
}

static __device__ __forceinline__ void ldm4(uint32_t* r, uint32_t addr) {
    asm volatile("ldmatrix.sync.aligned.m8n8.x4.shared.b16 {%0,%1,%2,%3}, [%4];"
                 : "=r"(r[0]), "=r"(r[1]), "=r"(r[2]), "=r"(r[3]) : "r"(addr));
}

static __device__ __forceinline__ void ldm4t(uint32_t* r, uint32_t addr) {
    asm volatile("ldmatrix.sync.aligned.m8n8.x4.trans.shared.b16 {%0,%1,%2,%3}, [%4];"
                 : "=r"(r[0]), "=r"(r[1]), "=r"(r[2]), "=r"(r[3]) : "r"(addr));
}

static __device__ __forceinline__ void mma16816(float* c, const uint32_t* a,
                                                uint32_t b0, uint32_t b1) {
    asm volatile("mma.sync.aligned.m16n8k16.row.col.f32.bf16.bf16.f32 "
                 "{%0,%1,%2,%3}, {%4,%5,%6,%7}, {%8,%9}, {%0,%1,%2,%3};"
                 : "+f"(c[0]), "+f"(c[1]), "+f"(c[2]), "+f"(c[3])
                 : "r"(a[0]), "r"(a[1]), "r"(a[2]), "r"(a[3]), "r"(b0), "r"(b1));
}

static __device__ __forceinline__ uint32_t pack_hi(float a, float b) {
    return __byte_perm(__float_as_uint(a), __float_as_uint(b), 0x7632);
}
static __device__ __forceinline__ uint32_t pack_lo(float a, float b) {
    float ra = a - __uint_as_float(__float_as_uint(a) & 0xFFFF0000u);
    float rb = b - __uint_as_float(__float_as_uint(b) & 0xFFFF0000u);
    uint32_t r;
    asm("cvt.rn.satfinite.bf16x2.f32 %0, %1, %2;" : "=r"(r) : "f"(rb), "f"(ra));
    return r;
}

static __device__ __forceinline__ float ex2(float x) {
    float r;
    asm("ex2.approx.f32 %0, %1;" : "=f"(r) : "f"(x));
    return r;
}

static __device__ __forceinline__ void split_store(float x, ushort_t* ph,
                                                   ushort_t* pl) {
    uint32_t u = __float_as_uint(x);
    *ph = (ushort_t)(u >> 16);
    float lo = x - __uint_as_float(u & 0xFFFF0000u);
    ushort_t ls;
    asm("cvt.rn.satfinite.bf16.f32 %0, %1;" : "=h"(ls) : "f"(lo));
    *pl = ls;
}

#define CP_ASYNC(dst, src) \
    asm volatile("cp.async.cg.shared.global [%0], [%1], 16;" \
                 :: "r"(dst), "l"(src) : "memory")
#define CP_COMMIT() asm volatile("cp.async.commit_group;" ::: "memory")
#define CP_WAIT1() asm volatile("cp.async.wait_group 1;" ::: "memory")
#define CP_WAIT0() asm volatile("cp.async.wait_group 0;" ::: "memory")

// ---------------- input pre-split ------------------------------------------
__global__ __launch_bounds__(256) void split_f32(const float* __restrict__ src,
                                                 ushort_t* __restrict__ hi,
                                                 ushort_t* __restrict__ lo,
                                                 int n4) {
    int i = blockIdx.x * blockDim.x + threadIdx.x;
    if (i < n4) {
        float4 f = ((const float4*)src)[i];
        ((uint2*)hi)[i] = make_uint2(pack_hi(f.x, f.y), pack_hi(f.z, f.w));
        ((uint2*)lo)[i] = make_uint2(pack_lo(f.x, f.y), pack_lo(f.z, f.w));
    }
}

// =============== mma.sync GEMM (pre-split inputs, cp.async pipeline) ========
// C[M,N] = (Ah+Al)[M,K] * (Bh+Bl)[N,K]^T, 3-term. 128x128 tile, BK=32,
// 256 threads (8 warps = 4m x 2n). Double-buffered cp.async stages.
#define G_ROWB 80
#define G_TILE 10240
#define G_STAGE_B (4 * G_TILE)
#define G_SMEM (2 * G_STAGE_B + 128)

__global__ __launch_bounds__(256, 2) void gemm_mma_s(
    const ushort_t* __restrict__ Ah, const ushort_t* __restrict__ Al,
    const ushort_t* __restrict__ Bh, const ushort_t* __restrict__ Bl,
    float* __restrict__ C, int M, int N, int K) {
    extern __shared__ char dsm[];
    const uint32_t tile = (smem_u32(dsm) + 127u) & ~127u;

    const int tid = threadIdx.x;
    const int wid = tid >> 5;
    const int lane = tid & 31;
    const int wm = wid & 3;
    const int wn = wid >> 2;
    const int bm = blockIdx.y * 128;
    const int bn = blockIdx.x * 128;

    // loader: thread -> (row, half); each half-row = 16 ushorts = 2x16B
    const int row = tid >> 1;
    const int half = tid & 1;
    const ushort_t* pAh = Ah + (size_t)(bm + row) * K + half * 16;
    const ushort_t* pAl = Al + (size_t)(bm + row) * K + half * 16;
    const ushort_t* pBh = Bh + (size_t)(bn + row) * K + half * 16;
    const ushort_t* pBl = Bl + (size_t)(bn + row) * K + half * 16;
    const uint32_t s_row = (uint32_t)(row * G_ROWB + half * 32);

    const int r8 = lane & 7, sub = lane >> 3;
    const uint32_t a_off = (uint32_t)((wm * 32 + r8 + (sub & 1) * 8) * G_ROWB +
                                      (sub >> 1) * 16);
    const uint32_t b_off = (uint32_t)((wn * 64 + r8 + (sub >> 1) * 8) * G_ROWB +
                                      (sub & 1) * 16);

    float acc[2][8][4];
#pragma unroll
    for (int i = 0; i < 2; i++)
#pragma unroll
        for (int j = 0; j < 8; j++)
#pragma unroll
            for (int q = 0; q < 4; q++) acc[i][j][q] = 0.f;

    const int nch = K >> 5;

#define G_ISSUE(chunk, sb) do {                                               \
    const int _k0 = (chunk) << 5;                                             \
    CP_ASYNC((sb) + s_row,                   pAh + _k0);                      \
    CP_ASYNC((sb) + s_row + 16,              pAh + _k0 + 8);                  \
    CP_ASYNC((sb) + G_TILE + s_row,          pAl + _k0);                      \
    CP_ASYNC((sb) + G_TILE + s_row + 16,     pAl + _k0 + 8);                  \
    CP_ASYNC((sb) + 2 * G_TILE + s_row,      pBh + _k0);                      \
    CP_ASYNC((sb) + 2 * G_TILE + s_row + 16, pBh + _k0 + 8);                  \
    CP_ASYNC((sb) + 3 * G_TILE + s_row,      pBl + _k0);                      \
    CP_ASYNC((sb) + 3 * G_TILE + s_row + 16, pBl + _k0 + 8);                  \
} while (0)

    G_ISSUE(0, tile);              CP_COMMIT();
    G_ISSUE(1, tile + G_STAGE_B);  CP_COMMIT();

    for (int i = 0; i < nch; i++) {
        const uint32_t cur = tile + (uint32_t)(i & 1) * G_STAGE_B;
        if (i + 1 < nch) { CP_WAIT1(); } else { CP_WAIT0(); }
        __syncthreads();

#pragma unroll
        for (int ks = 0; ks < 2; ks++) {
            uint32_t ah[8], al[8];
            const uint32_t ka = cur + a_off + ks * 32;
            ldm4(ah,     ka);
            ldm4(ah + 4, ka + 16 * G_ROWB);
            ldm4(al,     ka + G_TILE);
            ldm4(al + 4, ka + G_TILE + 16 * G_ROWB);
#pragma unroll
            for (int g = 0; g < 4; g++) {
                uint32_t bh[4], bl[4];
                const uint32_t kb = cur + 2 * G_TILE + b_off + ks * 32 +
                                    g * (16 * G_ROWB);
                ldm4(bh, kb);
                ldm4(bl, kb + G_TILE);
#pragma unroll
                for (int ms = 0; ms < 2; ms++) {
                    mma16816(acc[ms][2 * g],     ah + 4 * ms, bh[0], bh[1]);
                    mma16816(acc[ms][2 * g + 1], ah + 4 * ms, bh[2], bh[3]);
                    mma16816(acc[ms][2 * g],     ah + 4 * ms, bl[0], bl[1]);
                    mma16816(acc[ms][2 * g + 1], ah + 4 * ms, bl[2], bl[3]);
                    mma16816(acc[ms][2 * g],     al + 4 * ms, bh[0], bh[1]);
                    mma16816(acc[ms][2 * g + 1], al + 4 * ms, bh[2], bh[3]);
                }
            }
        }
        __syncthreads();
        if (i + 2 < nch) {
            G_ISSUE(i + 2, cur);
            CP_COMMIT();
        }
    }
#undef G_ISSUE

    const int trow = lane >> 2;
    const int tcol = (lane & 3) * 2;
#pragma unroll
    for (int ms = 0; ms < 2; ms++) {
#pragma unroll
        for (int nf = 0; nf < 8; nf++) {
            const int r = bm + wm * 32 + ms * 16 + trow;
            const int c = bn + wn * 64 + nf * 8 + tcol;
            *(float2*)(C + (size_t)r * N + c) =
                make_float2(acc[ms][nf][0], acc[ms][nf][1]);
            *(float2*)(C + (size_t)(r + 8) * N + c) =
                make_float2(acc[ms][nf][2], acc[ms][nf][3]);
        }
    }
}

// ---------------- RoPE + head transpose + bf16 split ------------------------
// Q additionally scaled by HD^-0.5 * log2(e) so attention runs in base-2.
__global__ __launch_bounds__(256) void rope_split(const float* __restrict__ cosp,
                                                  const float* __restrict__ sinp) {
    const int token = blockIdx.x;
    const int b = token / Tdim;
    const int t = token % Tdim;
    __shared__ float cs[HD], sn[HD];
    if (threadIdx.x < HD) {
        cs[threadIdx.x] = cosp[(size_t)token * HD + threadIdx.x];
        sn[threadIdx.x] = sinp[(size_t)token * HD + threadIdx.x];
    }
    __syncthreads();

    const float qsc = 0.125f * 1.4426950408889634f;
    for (int p = threadIdx.x; p < NH * 32; p += 256) {
        const int hh = p >> 5;
        const int d  = p & 31;
        const size_t src = (size_t)token * (NH * HD) + hh * HD + d;
        float x1 = g_qt[src];
        float x2 = g_qt[src + 32];
        float c = cs[d], s = sn[d];
        const size_t base = ((size_t)(b * NH + hh) * Tdim + t) * HD;
        float y1 = (x1 * c - x2 * s) * qsc;
        float y2 = (x2 * c + x1 * s) * qsc;
        split_store(y1, &g_qh[base + d],      &g_ql[base + d]);
        split_store(y2, &g_qh[base + d + 32], &g_ql[base + d + 32]);
    }
    for (int p = threadIdx.x; p < NKV * 32; p += 256) {
        const int hh = p >> 5;
        const int d  = p & 31;
        const size_t src = (size_t)token * (NKV * HD) + hh * HD + d;
        float x1 = g_kt[src];
        float x2 = g_kt[src + 32];
        float c = cs[d], s = sn[d];
        const size_t base = ((size_t)(b * NKV + hh) * Tdim + t) * HD;
        float y1 = x1 * c - x2 * s;
        float y2 = x2 * c + x1 * s;
        split_store(y1, &g_kh[base + d],      &g_kl[base + d]);
        split_store(y2, &g_kh[base + d + 32], &g_kl[base + d + 32]);
    }
    for (int e = threadIdx.x; e < NKV * HD; e += 256) {
        const int hh = e >> 6;
        const int d  = e & 63;
        float v = g_vt[(size_t)token * (NKV * HD) + e];
        const size_t base = ((size_t)(b * NKV + hh) * Tdim + t) * HD;
        split_store(v, &g_vh[base + d], &g_vl[base + d]);
    }
}

// ---------------- Flash attention (tensor cores, causal, GQA) ---------------
// Br=128, Bc=64, 256 threads (8 warps; warp w owns rows w*16..w*16+15).
// smem ushort offsets: Qh 0, Ql 9216, Kh 18432, Kl 23040, Vh 27648, Vl 32256.
#define FB 144
#define FA_SMEM 73728

__global__ __launch_bounds__(256, 2) void flash_mma() {
    extern __shared__ ushort_t fsm[];
    const uint32_t s0 = smem_u32(fsm);
    const uint32_t sQh = s0, sQl = s0 + 18432;
    const uint32_t sKh = s0 + 36864, sKl = s0 + 46080;
    const uint32_t sVh = s0 + 55296, sVl = s0 + 64512;

    const int tid = threadIdx.x;
    const int lane = tid & 31;
    const int w = tid >> 5;
    const int qtile = (int)gridDim.x - 1 - (int)blockIdx.x;  // big first
    const int bh = blockIdx.y;
    const int b = bh / NH;
    const int h = bh % NH;
    const int kvh = h / (NH / NKV);

    const ushort_t* qhp = g_qh + ((size_t)bh * Tdim + qtile * 128) * HD;
    const ushort_t* qlp = g_ql + ((size_t)bh * Tdim + qtile * 128) * HD;
    const size_t kvbase = (size_t)(b * NKV + kvh) * Tdim * HD;

    // stage Q (128x64 bf16 x2): 1024 uint4 per array, 4 per thread
#pragma unroll
    for (int j = 0; j < 4; j++) {
        const int idx = tid + j * 256;
        const int qr = idx >> 3;
        const int qc = idx & 7;
        *(uint4*)(fsm + qr * 72 + qc * 8)        = *(const uint4*)(qhp + qr * HD + qc * 8);
        *(uint4*)(fsm + 9216 + qr * 72 + qc * 8) = *(const uint4*)(qlp + qr * HD + qc * 8);
    }

    const int r8 = lane & 7, sub = lane >> 3;
    const uint32_t a_off = (uint32_t)((w * 16 + r8 + ((sub & 1) << 3)) * FB +
                                      ((sub >> 1) << 4));
    const uint32_t b_off = (uint32_t)((r8 + ((sub >> 1) << 3)) * FB +
                                      ((sub & 1) << 4));
    const uint32_t v_off = (uint32_t)(((lane & 8) + (lane & 7)) * FB +
                                      (lane >> 4) * 16);

    float m0 = -1e30f, m1 = -1e30f, l0 = 0.f, l1 = 0.f;
    float o[8][4];
#pragma unroll
    for (int t = 0; t < 8; t++)
#pragma unroll
        for (int e = 0; e < 4; e++) o[t][e] = 0.f;

    const int ktmax = 2 * qtile + 1;
    for (int kt = 0; kt <= ktmax; kt++) {
        // global K/V loads to regs (512 uint4 per array, 2 per thread)
        uint4 rkh[2], rkl[2], rvh[2], rvl[2];
        const ushort_t* kh = g_kh + kvbase + (size_t)kt * 64 * HD;
        const ushort_t* kl = g_kl + kvbase + (size_t)kt * 64 * HD;
        const ushort_t* vh = g_vh + kvbase + (size_t)kt * 64 * HD;
        const ushort_t* vl = g_vl + kvbase + (size_t)kt * 64 * HD;
#pragma unroll
        for (int j = 0; j < 2; j++) {
            const int idx = tid + j * 256;
            const int off = (idx >> 3) * HD + (idx & 7) * 8;
            rkh[j] = *(const uint4*)(kh + off);
            rkl[j] = *(const uint4*)(kl + off);
            rvh[j] = *(const uint4*)(vh + off);
            rvl[j] = *(const uint4*)(vl + off);
        }
        __syncthreads();   // prev compute done (and Q staging on iter 0)
#pragma unroll
        for (int j = 0; j < 2; j++) {
            const int idx = tid + j * 256;
            const int so = (idx >> 3) * 72 + (idx & 7) * 8;
            *(uint4*)(fsm + 18432 + so) = rkh[j];
            *(uint4*)(fsm + 23040 + so) = rkl[j];
            *(uint4*)(fsm + 27648 + so) = rvh[j];
            *(uint4*)(fsm + 32256 + so) = rvl[j];
        }
        __syncthreads();

        // --- S = Q K^T (3x split, base-2 logits) ---
        float sa[8][4];
#pragma unroll
        for (int t = 0; t < 8; t++)
#pragma unroll
            for (int e = 0; e < 4; e++) sa[t][e] = 0.f;

#pragma unroll
        for (int ks = 0; ks < 4; ks++) {
            uint32_t aqh[4], aql[4];
            ldm4(aqh, sQh + a_off + ks * 32);
            ldm4(aql, sQl + a_off + ks * 32);
#pragma unroll
            for (int g = 0; g < 4; g++) {
                uint32_t kbh[4], kbl[4];
                const uint32_t kb = sKh + b_off + ks * 32 + g * (16 * FB);
                ldm4(kbh, kb);
                ldm4(kbl, kb + 9216);
                mma16816(sa[2 * g],     aqh, kbh[0], kbh[1]);
                mma16816(sa[2 * g + 1], aqh, kbh[2], kbh[3]);
                mma16816(sa[2 * g],     aqh, kbl[0], kbl[1]);
                mma16816(sa[2 * g + 1], aqh, kbl[2], kbl[3]);
                mma16816(sa[2 * g],     aql, kbh[0], kbh[1]);
                mma16816(sa[2 * g + 1], aql, kbh[2], kbh[3]);
            }
        }

        // --- causal mask (last two tiles only) ---
        if (kt >= 2 * qtile) {
            const int row0 = qtile * 128 + w * 16 + (lane >> 2);
            const int cb = kt * 64 + (lane & 3) * 2;
#pragma unroll
            for (int t = 0; t < 8; t++) {
                const int c0 = cb + t * 8;
                if (c0 > row0)         sa[t][0] = -1e30f;
                if (c0 + 1 > row0)     sa[t][1] = -1e30f;
                if (c0 > row0 + 8)     sa[t][2] = -1e30f;
                if (c0 + 1 > row0 + 8) sa[t][3] = -1e30f;
            }
        }

        // --- online softmax (base 2) ---
        float rm0 = -1e30f, rm1 = -1e30f;
#pragma unroll
        for (int t = 0; t < 8; t++) {
            rm0 = fmaxf(rm0, fmaxf(sa[t][0], sa[t][1]));
            rm1 = fmaxf(rm1, fmaxf(sa[t][2], sa[t][3]));
        }
        rm0 = fmaxf(rm0, __shfl_xor_sync(0xffffffffu, rm0, 1));
        rm0 = fmaxf(rm0, __shfl_xor_sync(0xffffffffu, rm0, 2));
        rm1 = fmaxf(rm1, __shfl_xor_sync(0xffffffffu, rm1, 1));
        rm1 = fmaxf(rm1, __shfl_xor_sync(0xffffffffu, rm1, 2));
        const float mn0 = fmaxf(m0, rm0);
        const float mn1 = fmaxf(m1, rm1);
        const float al0 = ex2(m0 - mn0);
        const float al1 = ex2(m1 - mn1);
        m0 = mn0; m1 = mn1;
        float rs0 = 0.f, rs1 = 0.f;
#pragma unroll
        for (int t = 0; t < 8; t++) {
            sa[t][0] = ex2(sa[t][0] - mn0);
            sa[t][1] = ex2(sa[t][1] - mn0);
            sa[t][2] = ex2(sa[t][2] - mn1);
            sa[t][3] = ex2(sa[t][3] - mn1);
            rs0 += sa[t][0] + sa[t][1];
            rs1 += sa[t][2] + sa[t][3];
        }
        rs0 += __shfl_xor_sync(0xffffffffu, rs0, 1);
        rs0 += __shfl_xor_sync(0xffffffffu, rs0, 2);
        rs1 += __shfl_xor_sync(0xffffffffu, rs1, 1);
        rs1 += __shfl_xor_sync(0xffffffffu, rs1, 2);
        l0 = l0 * al0 + rs0;
        l1 = l1 * al1 + rs1;
#pragma unroll
        for (int t = 0; t < 8; t++) {
            o[t][0] *= al0; o[t][1] *= al0;
            o[t][2] *= al1; o[t][3] *= al1;
        }

        // --- repack P (hi + lo split, register-only) ---
        uint32_t ph[4][4], pl[4][4];
#pragma unroll
        for (int kc = 0; kc < 4; kc++) {
            const int t0 = 2 * kc, t1 = 2 * kc + 1;
            ph[kc][0] = pack_hi(sa[t0][0], sa[t0][1]);
            ph[kc][1] = pack_hi(sa[t0][2], sa[t0][3]);
            ph[kc][2] = pack_hi(sa[t1][0], sa[t1][1]);
            ph[kc][3] = pack_hi(sa[t1][2], sa[t1][3]);
            pl[kc][0] = pack_lo(sa[t0][0], sa[t0][1]);
            pl[kc][1] = pack_lo(sa[t0][2], sa[t0][3]);
            pl[kc][2] = pack_lo(sa[t1][0], sa[t1][1]);
            pl[kc][3] = pack_lo(sa[t1][2], sa[t1][3]);
        }

        // --- O += P V (3x split) ---
#pragma unroll
        for (int kc = 0; kc < 4; kc++) {
#pragma unroll
            for (int tp = 0; tp < 4; tp++) {
                uint32_t vbh[4], vbl[4];
                const uint32_t va = sVh + v_off + kc * (16 * FB) + tp * 32;
                ldm4t(vbh, va);
                ldm4t(vbl, va + 9216);
                mma16816(o[2 * tp],     ph[kc], vbh[0], vbh[1]);
                mma16816(o[2 * tp + 1], ph[kc], vbh[2], vbh[3]);
                mma16816(o[2 * tp],     ph[kc], vbl[0], vbl[1]);
                mma16816(o[2 * tp + 1], ph[kc], vbl[2], vbl[3]);
                mma16816(o[2 * tp],     pl[kc], vbh[0], vbh[1]);
                mma16816(o[2 * tp + 1], pl[kc], vbh[2], vbh[3]);
            }
        }
    }

    // epilogue: normalize + split-write for the O projection
    const float inv0 = 1.0f / l0;
    const float inv1 = 1.0f / l1;
    const int row0 = qtile * 128 + w * 16 + (lane >> 2);
    const int colb = (lane & 3) * 2;
#pragma unroll
    for (int t = 0; t < 8; t++) {
        const int c = h * HD + t * 8 + colb;
        const size_t i0 = ((size_t)b * Tdim + row0) * (NH * HD) + c;
        const size_t i1 = ((size_t)b * Tdim + row0 + 8) * (NH * HD) + c;
        float a0 = o[t][0] * inv0, a1 = o[t][1] * inv0;
        float a2 = o[t][2] * inv1, a3 = o[t][3] * inv1;
        *(uint32_t*)(g_oh + i0) = pack_hi(a0, a1);
        *(uint32_t*)(g_ol + i0) = pack_lo(a0, a1);
        *(uint32_t*)(g_oh + i1) = pack_hi(a2, a3);
        *(uint32_t*)(g_ol + i1) = pack_lo(a2, a3);
    }
}

// ---------------- launch ----------------------------------------------------
extern "C" void kernel_launch(void* const* d_in, const int* in_sizes, int n_in,
                              void* d_out, int out_size) {
    const float* hidden = (const float*)d_in[0];
    const float* cosp   = (const float*)d_in[1];
    const float* sinp   = (const float*)d_in[2];
    const float* wq     = (const float*)d_in[3];
    const float* wk     = (const float*)d_in[4];
    const float* wv     = (const float*)d_in[5];
    const float* wo     = (const float*)d_in[6];
    float* out = (float*)d_out;

    float *qt, *kt, *vt;
    ushort_t *hh, *hl, *wqh, *wql, *wkh, *wkl, *wvh, *wvl, *woh, *wol, *oh, *ol;
    cudaGetSymbolAddress((void**)&qt,  g_qt);
    cudaGetSymbolAddress((void**)&kt,  g_kt);
    cudaGetSymbolAddress((void**)&vt,  g_vt);
    cudaGetSymbolAddress((void**)&hh,  g_hh);
    cudaGetSymbolAddress((void**)&hl,  g_hl);
    cudaGetSymbolAddress((void**)&wqh, g_wqh);
    cudaGetSymbolAddress((void**)&wql, g_wql);
    cudaGetSymbolAddress((void**)&wkh, g_wkh);
    cudaGetSymbolAddress((void**)&wkl, g_wkl);
    cudaGetSymbolAddress((void**)&wvh, g_wvh);
    cudaGetSymbolAddress((void**)&wvl, g_wvl);
    cudaGetSymbolAddress((void**)&woh, g_woh);
    cudaGetSymbolAddress((void**)&wol, g_wol);
    cudaGetSymbolAddress((void**)&oh,  g_oh);
    cudaGetSymbolAddress((void**)&ol,  g_ol);

    cudaFuncSetAttribute(gemm_mma_s, cudaFuncAttributeMaxDynamicSharedMemorySize,
                         G_SMEM);
    cudaFuncSetAttribute(flash_mma, cudaFuncAttributeMaxDynamicSharedMemorySize,
                         FA_SMEM);

    // pre-split inputs (bf16 hi/lo)
    split_f32<<<(BT * HID / 4 + 255) / 256, 256>>>(hidden, hh, hl, BT * HID / 4);
    split_f32<<<(HID * HID / 4 + 255) / 256, 256>>>(wq, wqh, wql, HID * HID / 4);
    split_f32<<<(NKV * HD * HID / 4 + 255) / 256, 256>>>(wk, wkh, wkl, NKV * HD * HID / 4);
    split_f32<<<(NKV * HD * HID / 4 + 255) / 256, 256>>>(wv, wvh, wvl, NKV * HD * HID / 4);
    split_f32<<<(HID * HID / 4 + 255) / 256, 256>>>(wo, woh, wol, HID * HID / 4);

    // QKV projections
    gemm_mma_s<<<dim3(16, 32), 256, G_SMEM>>>(hh, hl, wqh, wql, qt, BT, NH * HD, HID);
    gemm_mma_s<<<dim3(4, 32),  256, G_SMEM>>>(hh, hl, wkh, wkl, kt, BT, NKV * HD, HID);
    gemm_mma_s<<<dim3(4, 32),  256, G_SMEM>>>(hh, hl, wvh, wvl, vt, BT, NKV * HD, HID);

    // RoPE + transpose + split
    rope_split<<<BT, 256>>>(cosp, sinp);

    // Flash attention (tensor cores, Br=128)
    flash_mma<<<dim3(Tdim / 128, Bdim * NH), 256, FA_SMEM>>>();

    // Output projection
    gemm_mma_s<<<dim3(16, 32), 256, G_SMEM>>>(oh, ol, woh, wol, out, BT, HID, HID);
}